// round 3
// baseline (speedup 1.0000x reference)
#include <cuda_runtime.h>
#include <cuda_bf16.h>
#include <cstdint>
#include <cstddef>

// ---------------- problem constants ----------------
#define HID   3584
#define NH    28
#define NKV   4
#define HD    128
#define SEQ   2048
#define DQ    (NH*HD)     // 3584
#define DKV   (NKV*HD)    // 512
#define GRP   128

// ---------------- device scratch (no allocs allowed) ----------------
__device__ float g_Wq[HID * DQ];
__device__ float g_Wk[HID * DKV];
__device__ float g_Wv[HID * DKV];
__device__ float g_Wo[DQ * HID];
__device__ float g_Q [SEQ * DQ];
__device__ float g_K [SEQ * DKV];
__device__ float g_V [SEQ * DKV];
__device__ float g_Ob[SEQ * DQ];

// ---------------- AWQ int4 dequant ----------------
// qw: [din, dout/8] int32 (8 nibbles, col j*8+i uses shift 4*i)
// qz: [din/G, dout/8] int32, sc: [din/G, dout] f32
// W out: [din, dout] row-major f32
__global__ void dequant_kernel(const int* __restrict__ qw, const int* __restrict__ qz,
                               const float* __restrict__ sc, float* __restrict__ W,
                               int din, int dout) {
    int dout8 = dout >> 3;
    int idx = blockIdx.x * blockDim.x + threadIdx.x;
    if (idx >= din * dout8) return;
    int row  = idx / dout8;
    int pcol = idx - row * dout8;
    unsigned qwv = (unsigned)qw[idx];
    int grp = row >> 7;  // /GRP
    unsigned qzv = (unsigned)qz[grp * dout8 + pcol];
    const float* scp = sc + (size_t)grp * dout + pcol * 8;
    float* wp = W + (size_t)row * dout + pcol * 8;
#pragma unroll
    for (int i = 0; i < 8; i++) {
        int w = (qwv >> (4 * i)) & 0xF;
        int z = (qzv >> (4 * i)) & 0xF;
        wp[i] = (float)(w - z) * scp[i];
    }
}

// ---------------- SGEMM: C[M,N] = A[M,K] @ B[K,N] (+bias) ----------------
// 128x128 tile, BK=8, 256 threads, 8x8 microtile per thread.
template <bool HAS_BIAS>
__global__ __launch_bounds__(256) void sgemm128(const float* __restrict__ A,
                                                const float* __restrict__ B,
                                                const float* __restrict__ bias,
                                                float* __restrict__ C,
                                                int M, int N, int K) {
    __shared__ float As[8][128];
    __shared__ float Bs[8][128];
    int tid = threadIdx.x;
    int col0 = blockIdx.x * 128;
    int row0 = blockIdx.y * 128;

    int aRow = tid >> 1;                  // 0..127
    int aCol = (tid & 1) * 4;             // 0 or 4
    int bRow = tid >> 5;                  // 0..7
    int bCol = (tid & 31) * 4;            // 0..124
    int tx = tid & 15, ty = tid >> 4;

    const float* Aptr = A + (size_t)(row0 + aRow) * K + aCol;
    const float* Bptr = B + (size_t)bRow * N + col0 + bCol;

    float acc[8][8];
#pragma unroll
    for (int i = 0; i < 8; i++)
#pragma unroll
        for (int j = 0; j < 8; j++) acc[i][j] = 0.f;

    for (int k0 = 0; k0 < K; k0 += 8) {
        float4 a4 = *(const float4*)(Aptr + k0);
        float4 b4 = *(const float4*)(Bptr + (size_t)k0 * N);
        As[aCol + 0][aRow] = a4.x;
        As[aCol + 1][aRow] = a4.y;
        As[aCol + 2][aRow] = a4.z;
        As[aCol + 3][aRow] = a4.w;
        *(float4*)&Bs[bRow][bCol] = b4;
        __syncthreads();
#pragma unroll
        for (int kk = 0; kk < 8; kk++) {
            float ar[8], br[8];
            *(float4*)&ar[0] = *(float4*)&As[kk][ty * 8];
            *(float4*)&ar[4] = *(float4*)&As[kk][ty * 8 + 4];
            *(float4*)&br[0] = *(float4*)&Bs[kk][tx * 8];
            *(float4*)&br[4] = *(float4*)&Bs[kk][tx * 8 + 4];
#pragma unroll
            for (int i = 0; i < 8; i++)
#pragma unroll
                for (int j = 0; j < 8; j++) acc[i][j] += ar[i] * br[j];
        }
        __syncthreads();
    }

#pragma unroll
    for (int i = 0; i < 8; i++) {
        int r = row0 + ty * 8 + i;
        float* cp = C + (size_t)r * N + col0 + tx * 8;
#pragma unroll
        for (int j = 0; j < 8; j += 4) {
            float4 v;
            v.x = acc[i][j + 0]; v.y = acc[i][j + 1];
            v.z = acc[i][j + 2]; v.w = acc[i][j + 3];
            if (HAS_BIAS) {
                const float* bp = bias + col0 + tx * 8 + j;
                v.x += bp[0]; v.y += bp[1]; v.z += bp[2]; v.w += bp[3];
            }
            *(float4*)(cp + j) = v;
        }
    }
}

// ---------------- RoPE (in-place on Q [S,NH*HD] and K [S,NKV*HD]) ----------------
__global__ void rope_kernel(float* __restrict__ Q, float* __restrict__ K,
                            const int* __restrict__ pos) {
    int idx = blockIdx.x * blockDim.x + threadIdx.x;
    const int total = SEQ * (NH + NKV) * (HD / 2);
    if (idx >= total) return;
    int d = idx & 63;
    int h = (idx >> 6) & 31;
    int s = idx >> 11;
    // inv_freq = theta^(-2d/HD) = exp(-d/64 * ln(1e6))
    float inv = expf((float)d * (-13.815510557964274f / 64.0f));
    float ang = (float)pos[s] * inv;
    float si, co;
    sincosf(ang, &si, &co);
    float* p;
    if (h < NH) p = Q + (size_t)s * DQ + h * HD;
    else        p = K + (size_t)s * DKV + (h - NH) * HD;
    float x0 = p[d];
    float x1 = p[d + 64];
    p[d]      = x0 * co - x1 * si;
    p[d + 64] = x1 * co + x0 * si;
}

// ---------------- causal GQA flash attention ----------------
// Q: [S, NH*HD], K/V: [S, NKV*HD], O: [S, NH*HD]
#define QB  64
#define KBL 64
#define KST 132   // padded row stride for Q/K/V tiles (floats)
#define SST 68    // padded row stride for score tile

#define ATTN_SMEM_FLOATS (3 * QB * KST + QB * SST + 3 * QB)
#define ATTN_SMEM_BYTES  (ATTN_SMEM_FLOATS * 4)

__global__ __launch_bounds__(256) void attn_kernel(const float* __restrict__ Q,
                                                   const float* __restrict__ K,
                                                   const float* __restrict__ V,
                                                   float* __restrict__ O) {
    extern __shared__ float sm[];
    float* Qs   = sm;
    float* Ks   = Qs + QB * KST;
    float* Vs   = Ks + KBL * KST;
    float* Ss   = Vs + KBL * KST;
    float* rowM = Ss + QB * SST;
    float* rowL = rowM + QB;
    float* rowC = rowL + QB;

    int qb = blockIdx.x;           // 0..31
    int h  = blockIdx.y;           // 0..27
    int hk = h / (NH / NKV);       // GQA: 7 q-heads per kv-head
    int tid = threadIdx.x;
    int tx = tid & 15, ty = tid >> 4;

    // load Q tile (64 x 128)
    for (int i = tid; i < QB * (HD / 4); i += 256) {
        int r  = i >> 5;            // HD/4 = 32
        int d4 = (i & 31) << 2;
        float4 v = *(const float4*)&Q[(size_t)(qb * QB + r) * DQ + h * HD + d4];
        *(float4*)&Qs[r * KST + d4] = v;
    }
    if (tid < QB) { rowM[tid] = -1e30f; rowL[tid] = 0.f; }

    float acc[4][8];
#pragma unroll
    for (int i = 0; i < 4; i++)
#pragma unroll
        for (int j = 0; j < 8; j++) acc[i][j] = 0.f;

    const float scale = 0.08838834764831845f;  // 1/sqrt(128)

    for (int kb = 0; kb <= qb; kb++) {
        __syncthreads();  // protect Qs (iter 0) / Ks,Vs,Ss reuse (iter >0)
        // load K, V tiles (64 x 128)
        for (int i = tid; i < KBL * (HD / 4); i += 256) {
            int r  = i >> 5;
            int d4 = (i & 31) << 2;
            size_t g = (size_t)(kb * KBL + r) * DKV + hk * HD + d4;
            *(float4*)&Ks[r * KST + d4] = *(const float4*)&K[g];
            *(float4*)&Vs[r * KST + d4] = *(const float4*)&V[g];
        }
        __syncthreads();

        // scores: S[64,64], each thread does 4x4
        float s[4][4];
#pragma unroll
        for (int i = 0; i < 4; i++)
#pragma unroll
            for (int j = 0; j < 4; j++) s[i][j] = 0.f;

        for (int d0 = 0; d0 < HD; d0 += 4) {
            float4 q4[4], k4[4];
#pragma unroll
            for (int i = 0; i < 4; i++) q4[i] = *(float4*)&Qs[(ty * 4 + i) * KST + d0];
#pragma unroll
            for (int j = 0; j < 4; j++) k4[j] = *(float4*)&Ks[(tx * 4 + j) * KST + d0];
#pragma unroll
            for (int i = 0; i < 4; i++)
#pragma unroll
                for (int j = 0; j < 4; j++) {
                    s[i][j] += q4[i].x * k4[j].x;
                    s[i][j] += q4[i].y * k4[j].y;
                    s[i][j] += q4[i].z * k4[j].z;
                    s[i][j] += q4[i].w * k4[j].w;
                }
        }
        bool diag = (kb == qb);
#pragma unroll
        for (int i = 0; i < 4; i++) {
            int gi = ty * 4 + i;
#pragma unroll
            for (int j = 0; j < 4; j++) {
                int gj = tx * 4 + j;
                float v = s[i][j] * scale;
                if (diag && gj > gi) v = -1e30f;
                Ss[gi * SST + gj] = v;
            }
        }
        __syncthreads();

        // online softmax: one thread per row
        if (tid < QB) {
            int r = tid;
            float mOld = rowM[r];
            float mx = mOld;
#pragma unroll 8
            for (int j = 0; j < KBL; j++) mx = fmaxf(mx, Ss[r * SST + j]);
            float corr = __expf(mOld - mx);
            float l = rowL[r] * corr;
#pragma unroll 8
            for (int j = 0; j < KBL; j++) {
                float p = __expf(Ss[r * SST + j] - mx);
                Ss[r * SST + j] = p;
                l += p;
            }
            rowM[r] = mx; rowL[r] = l; rowC[r] = corr;
        }
        __syncthreads();

        // rescale + accumulate O += P @ V
#pragma unroll
        for (int i = 0; i < 4; i++) {
            float cr = rowC[ty * 4 + i];
#pragma unroll
            for (int j = 0; j < 8; j++) acc[i][j] *= cr;
        }
        for (int kk = 0; kk < KBL; kk++) {
            float4 v0 = *(float4*)&Vs[kk * KST + tx * 8];
            float4 v1 = *(float4*)&Vs[kk * KST + tx * 8 + 4];
#pragma unroll
            for (int i = 0; i < 4; i++) {
                float p = Ss[(ty * 4 + i) * SST + kk];
                acc[i][0] += p * v0.x; acc[i][1] += p * v0.y;
                acc[i][2] += p * v0.z; acc[i][3] += p * v0.w;
                acc[i][4] += p * v1.x; acc[i][5] += p * v1.y;
                acc[i][6] += p * v1.z; acc[i][7] += p * v1.w;
            }
        }
    }

    // finalize: divide by l, write out
#pragma unroll
    for (int i = 0; i < 4; i++) {
        float inv = 1.0f / rowL[ty * 4 + i];
        int r = qb * QB + ty * 4 + i;
        size_t g = (size_t)r * DQ + h * HD + tx * 8;
        float4 o0, o1;
        o0.x = acc[i][0] * inv; o0.y = acc[i][1] * inv;
        o0.z = acc[i][2] * inv; o0.w = acc[i][3] * inv;
        o1.x = acc[i][4] * inv; o1.y = acc[i][5] * inv;
        o1.z = acc[i][6] * inv; o1.w = acc[i][7] * inv;
        *(float4*)&O[g]     = o0;
        *(float4*)&O[g + 4] = o1;
    }
}

// ---------------- launch ----------------
extern "C" void kernel_launch(void* const* d_in, const int* in_sizes, int n_in,
                              void* d_out, int out_size) {
    const float* x    = (const float*)d_in[0];
    const int*   pos  = (const int*)d_in[1];
    const int*   qw_q = (const int*)d_in[2];
    const int*   qz_q = (const int*)d_in[3];
    const float* sc_q = (const float*)d_in[4];
    const float* b_q  = (const float*)d_in[5];
    const int*   qw_k = (const int*)d_in[6];
    const int*   qz_k = (const int*)d_in[7];
    const float* sc_k = (const float*)d_in[8];
    const float* b_k  = (const float*)d_in[9];
    const int*   qw_v = (const int*)d_in[10];
    const int*   qz_v = (const int*)d_in[11];
    const float* sc_v = (const float*)d_in[12];
    const float* b_v  = (const float*)d_in[13];
    const int*   qw_o = (const int*)d_in[14];
    const int*   qz_o = (const int*)d_in[15];
    const float* sc_o = (const float*)d_in[16];
    float* out = (float*)d_out;

    float *Wq, *Wk, *Wv, *Wo, *Qb, *Kb, *Vb, *Ob;
    cudaGetSymbolAddress((void**)&Wq, g_Wq);
    cudaGetSymbolAddress((void**)&Wk, g_Wk);
    cudaGetSymbolAddress((void**)&Wv, g_Wv);
    cudaGetSymbolAddress((void**)&Wo, g_Wo);
    cudaGetSymbolAddress((void**)&Qb, g_Q);
    cudaGetSymbolAddress((void**)&Kb, g_K);
    cudaGetSymbolAddress((void**)&Vb, g_V);
    cudaGetSymbolAddress((void**)&Ob, g_Ob);

    cudaFuncSetAttribute(attn_kernel, cudaFuncAttributeMaxDynamicSharedMemorySize,
                         ATTN_SMEM_BYTES);

    // dequant all 4 weight matrices
    {
        int cnt_big = HID * (DQ / 8);   // 1,605,632
        int cnt_kv  = HID * (DKV / 8);  // 229,376
        dequant_kernel<<<(cnt_big + 255) / 256, 256>>>(qw_q, qz_q, sc_q, Wq, HID, DQ);
        dequant_kernel<<<(cnt_kv  + 255) / 256, 256>>>(qw_k, qz_k, sc_k, Wk, HID, DKV);
        dequant_kernel<<<(cnt_kv  + 255) / 256, 256>>>(qw_v, qz_v, sc_v, Wv, HID, DKV);
        dequant_kernel<<<(cnt_big + 255) / 256, 256>>>(qw_o, qz_o, sc_o, Wo, DQ, HID);
    }

    // projections (+bias)
    sgemm128<true><<<dim3(DQ / 128, SEQ / 128), 256>>>(x, Wq, b_q, Qb, SEQ, DQ, HID);
    sgemm128<true><<<dim3(DKV / 128, SEQ / 128), 256>>>(x, Wk, b_k, Kb, SEQ, DKV, HID);
    sgemm128<true><<<dim3(DKV / 128, SEQ / 128), 256>>>(x, Wv, b_v, Vb, SEQ, DKV, HID);

    // RoPE on Q and K
    {
        int total = SEQ * (NH + NKV) * (HD / 2);
        rope_kernel<<<(total + 255) / 256, 256>>>(Qb, Kb, pos);
    }

    // causal GQA attention
    attn_kernel<<<dim3(SEQ / QB, NH), 256, ATTN_SMEM_BYTES>>>(Qb, Kb, Vb, Ob);

    // output projection (no bias) straight into d_out
    sgemm128<false><<<dim3(HID / 128, SEQ / 128), 256>>>(Ob, Wo, nullptr, out, SEQ, HID, DQ);
}

// round 5
// speedup vs baseline: 1.5272x; 1.5272x over previous
#include <cuda_runtime.h>
#include <cuda_bf16.h>
#include <cstdint>
#include <cstddef>

// ---------------- problem constants ----------------
#define HID   3584
#define NH    28
#define NKV   4
#define HD    128
#define SEQ   2048
#define DQ    (NH*HD)     // 3584
#define DKV   (NKV*HD)    // 512
#define GRP   128

// ---------------- device scratch (hi/lo tf32 splits for MMA operands) ----------------
__device__ float g_Wq_h[HID * DQ],  g_Wq_l[HID * DQ];
__device__ float g_Wk_h[HID * DKV], g_Wk_l[HID * DKV];
__device__ float g_Wv_h[HID * DKV], g_Wv_l[HID * DKV];
__device__ float g_Wo_h[DQ * HID],  g_Wo_l[DQ * HID];
__device__ float g_X_h [SEQ * HID], g_X_l [SEQ * HID];
__device__ float g_Q [SEQ * DQ];
__device__ float g_K [SEQ * DKV];
__device__ float g_V [SEQ * DKV];
__device__ float g_Ob_h[SEQ * DQ], g_Ob_l[SEQ * DQ];

// ---------------- helpers ----------------
__device__ __forceinline__ float f2tff(float x) {
    unsigned u;
    asm("cvt.rna.tf32.f32 %0, %1;" : "=r"(u) : "f"(x));
    return __uint_as_float(u);
}

__device__ __forceinline__ unsigned sptr(const void* p) {
    return (unsigned)__cvta_generic_to_shared(p);
}

#define CP_ASYNC16(dst, src) \
    asm volatile("cp.async.cg.shared.global [%0], [%1], 16;\n" :: "r"(dst), "l"(src))
#define CP_COMMIT() asm volatile("cp.async.commit_group;\n")

#define MMA_TF32(C, Aa, Bb) \
    asm volatile("mma.sync.aligned.m16n8k8.row.col.f32.tf32.tf32.f32 " \
        "{%0,%1,%2,%3},{%4,%5,%6,%7},{%8,%9},{%0,%1,%2,%3};" \
        : "+f"(C[0]), "+f"(C[1]), "+f"(C[2]), "+f"(C[3]) \
        : "r"(Aa[0]), "r"(Aa[1]), "r"(Aa[2]), "r"(Aa[3]), "r"(Bb[0]), "r"(Bb[1]))

// ---------------- AWQ int4 dequant -> hi/lo tf32 split ----------------
__global__ void dequant_kernel(const int* __restrict__ qw, const int* __restrict__ qz,
                               const float* __restrict__ sc,
                               float* __restrict__ Wh, float* __restrict__ Wl,
                               int din, int dout) {
    int dout8 = dout >> 3;
    int idx = blockIdx.x * blockDim.x + threadIdx.x;
    if (idx >= din * dout8) return;
    int row  = idx / dout8;
    int pcol = idx - row * dout8;
    unsigned qwv = (unsigned)qw[idx];
    int grp = row >> 7;
    unsigned qzv = (unsigned)qz[grp * dout8 + pcol];
    const float* scp = sc + (size_t)grp * dout + pcol * 8;
    size_t base = (size_t)row * dout + pcol * 8;
#pragma unroll
    for (int i = 0; i < 8; i++) {
        int w = (qwv >> (4 * i)) & 0xF;
        int z = (qzv >> (4 * i)) & 0xF;
        float v = (float)(w - z) * scp[i];
        float h = f2tff(v);
        Wh[base + i] = h;
        Wl[base + i] = f2tff(v - h);
    }
}

// ---------------- split fp32 -> hi/lo tf32 ----------------
__global__ void split_kernel(const float* __restrict__ in,
                             float* __restrict__ hi, float* __restrict__ lo, int n) {
    int i = blockIdx.x * blockDim.x + threadIdx.x;
    if (i < n) {
        float v = in[i];
        float h = f2tff(v);
        hi[i] = h;
        lo[i] = f2tff(v - h);
    }
}

// ---------------- 3xTF32 tensor-core GEMM ----------------
// C[M,N] = A[M,K] @ B[K,N] (+bias), A/B given as hi/lo tf32 splits.
// 128x128x32 tile, 256 thr (8 warps 2x4), warp tile 64x32, cp.async double buffer.
#define BM 128
#define BN 128
#define BK 32
#define ASTR 36
#define BSTR 136
#define AS_SZ (BM*ASTR)              // 4608
#define BS_SZ (BK*BSTR)              // 4352
#define GSTAGE (2*AS_SZ + 2*BS_SZ)   // 17920 floats
#define GEMM_SMEM (2 * GSTAGE * 4)   // 143360 bytes

template <bool HAS_BIAS>
__global__ __launch_bounds__(256) void gemm3t(const float* __restrict__ Ah,
                                              const float* __restrict__ Al,
                                              const float* __restrict__ Bhh,
                                              const float* __restrict__ Bll,
                                              const float* __restrict__ bias,
                                              float* __restrict__ C,
                                              int M, int N, int K) {
    extern __shared__ float sm[];
    int tid  = threadIdx.x;
    int lane = tid & 31;
    int wid  = tid >> 5;
    int gid  = lane >> 2, tig = lane & 3;
    int warp_m = wid >> 2;   // 0..1
    int warp_n = wid & 3;    // 0..3

    int ar = tid >> 1;            // 0..127
    int ac = (tid & 1) * 16;      // 0 / 16
    int br = tid >> 3;            // 0..31
    int bc = (tid & 7) * 16;      // 0..112
    size_t aoff = (size_t)(blockIdx.y * BM + ar) * K + ac;
    size_t boff = (size_t)br * N + blockIdx.x * BN + bc;

    float acc[4][4][4];
#pragma unroll
    for (int mt = 0; mt < 4; mt++)
#pragma unroll
        for (int nt = 0; nt < 4; nt++)
#pragma unroll
            for (int i = 0; i < 4; i++) acc[mt][nt][i] = 0.f;

    const int NT = K / BK;

#define GEMM_ISSUE(kt, stage) do {                                          \
        float* S = sm + (stage) * GSTAGE;                                   \
        unsigned sah = sptr(S + ar * ASTR + ac);                            \
        unsigned sal = sah + AS_SZ * 4;                                     \
        unsigned sbh = sptr(S + 2 * AS_SZ + br * BSTR + bc);                \
        unsigned sbl = sbh + BS_SZ * 4;                                     \
        const float* agh = Ah  + aoff + (kt) * BK;                          \
        const float* agl = Al  + aoff + (kt) * BK;                          \
        const float* bgh = Bhh + boff + (size_t)(kt) * BK * N;              \
        const float* bgl = Bll + boff + (size_t)(kt) * BK * N;              \
        CP_ASYNC16(sah, agh);      CP_ASYNC16(sah + 16, agh + 4);           \
        CP_ASYNC16(sah + 32, agh + 8); CP_ASYNC16(sah + 48, agh + 12);      \
        CP_ASYNC16(sal, agl);      CP_ASYNC16(sal + 16, agl + 4);           \
        CP_ASYNC16(sal + 32, agl + 8); CP_ASYNC16(sal + 48, agl + 12);      \
        CP_ASYNC16(sbh, bgh);      CP_ASYNC16(sbh + 16, bgh + 4);           \
        CP_ASYNC16(sbh + 32, bgh + 8); CP_ASYNC16(sbh + 48, bgh + 12);      \
        CP_ASYNC16(sbl, bgl);      CP_ASYNC16(sbl + 16, bgl + 4);           \
        CP_ASYNC16(sbl + 32, bgl + 8); CP_ASYNC16(sbl + 48, bgl + 12);      \
        CP_COMMIT();                                                        \
    } while (0)

    GEMM_ISSUE(0, 0);

    for (int kt = 0; kt < NT; kt++) {
        int cur = kt & 1;
        if (kt + 1 < NT) {
            GEMM_ISSUE(kt + 1, 1 - cur);
            asm volatile("cp.async.wait_group 1;\n");
        } else {
            asm volatile("cp.async.wait_group 0;\n");
        }
        __syncthreads();

        const unsigned* Ash = (const unsigned*)(sm + cur * GSTAGE);
        const unsigned* Asl = Ash + AS_SZ;
        const unsigned* Bsh = Ash + 2 * AS_SZ;
        const unsigned* Bsl = Bsh + BS_SZ;

#pragma unroll
        for (int ks = 0; ks < 4; ks++) {
            int kk = ks * 8;
            unsigned ah[4][4], al[4][4], bh[4][2], bl[4][2];
#pragma unroll
            for (int mt = 0; mt < 4; mt++) {
                int o = (warp_m * 64 + mt * 16 + gid) * ASTR + kk + tig;
                ah[mt][0] = Ash[o];            ah[mt][1] = Ash[o + 8 * ASTR];
                ah[mt][2] = Ash[o + 4];        ah[mt][3] = Ash[o + 8 * ASTR + 4];
                al[mt][0] = Asl[o];            al[mt][1] = Asl[o + 8 * ASTR];
                al[mt][2] = Asl[o + 4];        al[mt][3] = Asl[o + 8 * ASTR + 4];
            }
#pragma unroll
            for (int nt = 0; nt < 4; nt++) {
                int o = (kk + tig) * BSTR + warp_n * 32 + nt * 8 + gid;
                bh[nt][0] = Bsh[o];            bh[nt][1] = Bsh[o + 4 * BSTR];
                bl[nt][0] = Bsl[o];            bl[nt][1] = Bsl[o + 4 * BSTR];
            }
#pragma unroll
            for (int mt = 0; mt < 4; mt++)
#pragma unroll
                for (int nt = 0; nt < 4; nt++) {
                    MMA_TF32(acc[mt][nt], ah[mt], bh[nt]);
                    MMA_TF32(acc[mt][nt], ah[mt], bl[nt]);
                    MMA_TF32(acc[mt][nt], al[mt], bh[nt]);
                }
        }
        __syncthreads();
    }

    // epilogue
#pragma unroll
    for (int mt = 0; mt < 4; mt++) {
        int row = blockIdx.y * BM + warp_m * 64 + mt * 16 + gid;
#pragma unroll
        for (int nt = 0; nt < 4; nt++) {
            int col = blockIdx.x * BN + warp_n * 32 + nt * 8 + tig * 2;
            float b0 = 0.f, b1 = 0.f;
            if (HAS_BIAS) { b0 = bias[col]; b1 = bias[col + 1]; }
            float2 v0 = { acc[mt][nt][0] + b0, acc[mt][nt][1] + b1 };
            float2 v1 = { acc[mt][nt][2] + b0, acc[mt][nt][3] + b1 };
            *(float2*)&C[(size_t)row * N + col]       = v0;
            *(float2*)&C[(size_t)(row + 8) * N + col] = v1;
        }
    }
#undef GEMM_ISSUE
}

// ---------------- RoPE (fp32, in-place) ----------------
__global__ void rope_kernel(float* __restrict__ Q, float* __restrict__ K,
                            const int* __restrict__ pos) {
    int idx = blockIdx.x * blockDim.x + threadIdx.x;
    const int total = SEQ * (NH + NKV) * (HD / 2);
    if (idx >= total) return;
    int d = idx & 63;
    int h = (idx >> 6) & 31;
    int s = idx >> 11;
    float inv = expf((float)d * (-13.815510557964274f / 64.0f));
    float ang = (float)pos[s] * inv;
    float si, co;
    sincosf(ang, &si, &co);
    float* p;
    if (h < NH) p = Q + (size_t)s * DQ + h * HD;
    else        p = K + (size_t)s * DKV + (h - NH) * HD;
    float x0 = p[d];
    float x1 = p[d + 64];
    p[d]      = x0 * co - x1 * si;
    p[d + 64] = x1 * co + x0 * si;
}

// ---------------- 3xTF32 causal GQA flash attention ----------------
// tiles: Q 64x128 (hi/lo), KV 64x128 (hi/lo, time-shared K then V), S 64x64 (hi/lo).
#define QB   64
#define QSTR 132
#define SSTR 68

// layout: Qh | Ql | KVh | KVl | Ss(hi in place) | Sl | rowM | rowL | rowC
#define A_QH 0
#define A_QL (A_QH + QB*QSTR)
#define A_KH (A_QL + QB*QSTR)
#define A_KL (A_KH + QB*QSTR)
#define A_SS (A_KL + QB*QSTR)
#define A_SL (A_SS + QB*SSTR)
#define A_RM (A_SL + QB*SSTR)
#define ATTN_SMEM_FLOATS (A_RM + 3*QB)
#define ATTN_SMEM_BYTES  (ATTN_SMEM_FLOATS * 4)   // 170,752 B

__global__ __launch_bounds__(256) void attn_tc(const float* __restrict__ Q,
                                               const float* __restrict__ K,
                                               const float* __restrict__ V,
                                               float* __restrict__ Oh,
                                               float* __restrict__ Ol) {
    extern __shared__ float sm[];
    float* Qh = sm + A_QH;
    float* Ql = sm + A_QL;
    float* KVh = sm + A_KH;
    float* KVl = sm + A_KL;
    float* Ss = sm + A_SS;
    float* Sl = sm + A_SL;
    float* rowM = sm + A_RM;
    float* rowL = rowM + QB;
    float* rowC = rowL + QB;
    const unsigned* QhU = (const unsigned*)Qh;
    const unsigned* QlU = (const unsigned*)Ql;
    const unsigned* KVhU = (const unsigned*)KVh;
    const unsigned* KVlU = (const unsigned*)KVl;
    const unsigned* SsU = (const unsigned*)Ss;
    const unsigned* SlU = (const unsigned*)Sl;

    int qb = blockIdx.x;
    int h  = blockIdx.y;
    int hk = h / (NH / NKV);
    int tid  = threadIdx.x;
    int lane = tid & 31;
    int wid  = tid >> 5;
    int gid  = lane >> 2, tig = lane & 3;
    int warp_m = wid >> 2;   // 0..1
    int warp_n = wid & 3;    // 0..3

    // load + split Q tile
#pragma unroll
    for (int j = 0; j < 8; j++) {
        int idx = tid + 256 * j;
        int r  = idx >> 5;
        int c4 = (idx & 31) << 2;
        float4 v = *(const float4*)&Q[(size_t)(qb * QB + r) * DQ + h * HD + c4];
        float4 hh = { f2tff(v.x), f2tff(v.y), f2tff(v.z), f2tff(v.w) };
        float4 ll = { f2tff(v.x - hh.x), f2tff(v.y - hh.y),
                      f2tff(v.z - hh.z), f2tff(v.w - hh.w) };
        *(float4*)&Qh[r * QSTR + c4] = hh;
        *(float4*)&Ql[r * QSTR + c4] = ll;
    }
    if (tid < QB) { rowM[tid] = -1e30f; rowL[tid] = 0.f; }

    float oacc[2][4][4];
#pragma unroll
    for (int mt = 0; mt < 2; mt++)
#pragma unroll
        for (int nt = 0; nt < 4; nt++)
#pragma unroll
            for (int i = 0; i < 4; i++) oacc[mt][nt][i] = 0.f;

    const float scale = 0.08838834764831845f;

    for (int kb = 0; kb <= qb; kb++) {
        __syncthreads();   // guard KV reuse from previous PV / Q load iter0
        // load + split K tile
#pragma unroll
        for (int j = 0; j < 8; j++) {
            int idx = tid + 256 * j;
            int r  = idx >> 5;
            int c4 = (idx & 31) << 2;
            float4 v = *(const float4*)&K[(size_t)(kb * QB + r) * DKV + hk * HD + c4];
            float4 hh = { f2tff(v.x), f2tff(v.y), f2tff(v.z), f2tff(v.w) };
            float4 ll = { f2tff(v.x - hh.x), f2tff(v.y - hh.y),
                          f2tff(v.z - hh.z), f2tff(v.w - hh.w) };
            *(float4*)&KVh[r * QSTR + c4] = hh;
            *(float4*)&KVl[r * QSTR + c4] = ll;
        }
        __syncthreads();

        // ---- S = Q @ K^T (3xTF32), warp tile 32x16 ----
        float sacc[2][2][4];
#pragma unroll
        for (int mt = 0; mt < 2; mt++)
#pragma unroll
            for (int nt = 0; nt < 2; nt++)
#pragma unroll
                for (int i = 0; i < 4; i++) sacc[mt][nt][i] = 0.f;

#pragma unroll
        for (int ks = 0; ks < 16; ks++) {
            int kk = ks * 8;
            unsigned ah[2][4], al[2][4], bh[2][2], bl[2][2];
#pragma unroll
            for (int mt = 0; mt < 2; mt++) {
                int o = (warp_m * 32 + mt * 16 + gid) * QSTR + kk + tig;
                ah[mt][0] = QhU[o];     ah[mt][1] = QhU[o + 8 * QSTR];
                ah[mt][2] = QhU[o + 4]; ah[mt][3] = QhU[o + 8 * QSTR + 4];
                al[mt][0] = QlU[o];     al[mt][1] = QlU[o + 8 * QSTR];
                al[mt][2] = QlU[o + 4]; al[mt][3] = QlU[o + 8 * QSTR + 4];
            }
#pragma unroll
            for (int nt = 0; nt < 2; nt++) {
                int o = (warp_n * 16 + nt * 8 + gid) * QSTR + kk + tig;
                bh[nt][0] = KVhU[o]; bh[nt][1] = KVhU[o + 4];
                bl[nt][0] = KVlU[o]; bl[nt][1] = KVlU[o + 4];
            }
#pragma unroll
            for (int mt = 0; mt < 2; mt++)
#pragma unroll
                for (int nt = 0; nt < 2; nt++) {
                    MMA_TF32(sacc[mt][nt], ah[mt], bh[nt]);
                    MMA_TF32(sacc[mt][nt], ah[mt], bl[nt]);
                    MMA_TF32(sacc[mt][nt], al[mt], bh[nt]);
                }
        }

        bool diag = (kb == qb);
#pragma unroll
        for (int mt = 0; mt < 2; mt++) {
            int r0 = warp_m * 32 + mt * 16 + gid;
#pragma unroll
            for (int nt = 0; nt < 2; nt++) {
                int c0 = warp_n * 16 + nt * 8 + tig * 2;
                float v00 = sacc[mt][nt][0] * scale;
                float v01 = sacc[mt][nt][1] * scale;
                float v10 = sacc[mt][nt][2] * scale;
                float v11 = sacc[mt][nt][3] * scale;
                if (diag) {
                    if (c0     > r0)     v00 = -1e30f;
                    if (c0 + 1 > r0)     v01 = -1e30f;
                    if (c0     > r0 + 8) v10 = -1e30f;
                    if (c0 + 1 > r0 + 8) v11 = -1e30f;
                }
                Ss[r0 * SSTR + c0]           = v00;
                Ss[r0 * SSTR + c0 + 1]       = v01;
                Ss[(r0 + 8) * SSTR + c0]     = v10;
                Ss[(r0 + 8) * SSTR + c0 + 1] = v11;
            }
        }
        __syncthreads();

        // ---- load + split V tile (overwrites K buffer; K fully consumed) ----
#pragma unroll
        for (int j = 0; j < 8; j++) {
            int idx = tid + 256 * j;
            int r  = idx >> 5;
            int c4 = (idx & 31) << 2;
            float4 v = *(const float4*)&V[(size_t)(kb * QB + r) * DKV + hk * HD + c4];
            float4 hh = { f2tff(v.x), f2tff(v.y), f2tff(v.z), f2tff(v.w) };
            float4 ll = { f2tff(v.x - hh.x), f2tff(v.y - hh.y),
                          f2tff(v.z - hh.z), f2tff(v.w - hh.w) };
            *(float4*)&KVh[r * QSTR + c4] = hh;
            *(float4*)&KVl[r * QSTR + c4] = ll;
        }

        // ---- online softmax (one thread per row), P split hi/lo ----
        if (tid < QB) {
            int r = tid;
            float mOld = rowM[r];
            float mx = mOld;
#pragma unroll 8
            for (int j = 0; j < QB; j++) mx = fmaxf(mx, Ss[r * SSTR + j]);
            float corr = __expf(mOld - mx);
            float l = rowL[r] * corr;
#pragma unroll 8
            for (int j = 0; j < QB; j++) {
                float p = __expf(Ss[r * SSTR + j] - mx);
                float ph = f2tff(p);
                Ss[r * SSTR + j] = ph;
                Sl[r * SSTR + j] = f2tff(p - ph);
                l += p;
            }
            rowM[r] = mx; rowL[r] = l; rowC[r] = corr;
        }
        __syncthreads();

        // ---- rescale O, then O += P @ V (3xTF32), warp tile 32x32 ----
#pragma unroll
        for (int mt = 0; mt < 2; mt++) {
            float cr0 = rowC[warp_m * 32 + mt * 16 + gid];
            float cr1 = rowC[warp_m * 32 + mt * 16 + gid + 8];
#pragma unroll
            for (int nt = 0; nt < 4; nt++) {
                oacc[mt][nt][0] *= cr0; oacc[mt][nt][1] *= cr0;
                oacc[mt][nt][2] *= cr1; oacc[mt][nt][3] *= cr1;
            }
        }
#pragma unroll
        for (int ks = 0; ks < 8; ks++) {
            int kk = ks * 8;
            unsigned ah[2][4], al[2][4], bh[4][2], bl[4][2];
#pragma unroll
            for (int mt = 0; mt < 2; mt++) {
                int o = (warp_m * 32 + mt * 16 + gid) * SSTR + kk + tig;
                ah[mt][0] = SsU[o];     ah[mt][1] = SsU[o + 8 * SSTR];
                ah[mt][2] = SsU[o + 4]; ah[mt][3] = SsU[o + 8 * SSTR + 4];
                al[mt][0] = SlU[o];     al[mt][1] = SlU[o + 8 * SSTR];
                al[mt][2] = SlU[o + 4]; al[mt][3] = SlU[o + 8 * SSTR + 4];
            }
#pragma unroll
            for (int nt = 0; nt < 4; nt++) {
                int o = (kk + tig) * QSTR + warp_n * 32 + nt * 8 + gid;
                bh[nt][0] = KVhU[o]; bh[nt][1] = KVhU[o + 4 * QSTR];
                bl[nt][0] = KVlU[o]; bl[nt][1] = KVlU[o + 4 * QSTR];
            }
#pragma unroll
            for (int mt = 0; mt < 2; mt++)
#pragma unroll
                for (int nt = 0; nt < 4; nt++) {
                    MMA_TF32(oacc[mt][nt], ah[mt], bh[nt]);
                    MMA_TF32(oacc[mt][nt], ah[mt], bl[nt]);
                    MMA_TF32(oacc[mt][nt], al[mt], bh[nt]);
                }
        }
    }

    // finalize: divide by l, write hi/lo split (feeds O-projection)
#pragma unroll
    for (int mt = 0; mt < 2; mt++) {
        int r0 = warp_m * 32 + mt * 16 + gid;
        float inv0 = 1.0f / rowL[r0];
        float inv1 = 1.0f / rowL[r0 + 8];
        int gr = qb * QB + r0;
#pragma unroll
        for (int nt = 0; nt < 4; nt++) {
            int c = h * HD + warp_n * 32 + nt * 8 + tig * 2;
            float o00 = oacc[mt][nt][0] * inv0, o01 = oacc[mt][nt][1] * inv0;
            float o10 = oacc[mt][nt][2] * inv1, o11 = oacc[mt][nt][3] * inv1;
            float h00 = f2tff(o00), h01 = f2tff(o01);
            float h10 = f2tff(o10), h11 = f2tff(o11);
            float2 vh0 = { h00, h01 }, vh1 = { h10, h11 };
            float2 vl0 = { f2tff(o00 - h00), f2tff(o01 - h01) };
            float2 vl1 = { f2tff(o10 - h10), f2tff(o11 - h11) };
            *(float2*)&Oh[(size_t)gr * DQ + c]       = vh0;
            *(float2*)&Oh[(size_t)(gr + 8) * DQ + c] = vh1;
            *(float2*)&Ol[(size_t)gr * DQ + c]       = vl0;
            *(float2*)&Ol[(size_t)(gr + 8) * DQ + c] = vl1;
        }
    }
}

// ---------------- launch ----------------
extern "C" void kernel_launch(void* const* d_in, const int* in_sizes, int n_in,
                              void* d_out, int out_size) {
    const float* x    = (const float*)d_in[0];
    const int*   pos  = (const int*)d_in[1];
    const int*   qw_q = (const int*)d_in[2];
    const int*   qz_q = (const int*)d_in[3];
    const float* sc_q = (const float*)d_in[4];
    const float* b_q  = (const float*)d_in[5];
    const int*   qw_k = (const int*)d_in[6];
    const int*   qz_k = (const int*)d_in[7];
    const float* sc_k = (const float*)d_in[8];
    const float* b_k  = (const float*)d_in[9];
    const int*   qw_v = (const int*)d_in[10];
    const int*   qz_v = (const int*)d_in[11];
    const float* sc_v = (const float*)d_in[12];
    const float* b_v  = (const float*)d_in[13];
    const int*   qw_o = (const int*)d_in[14];
    const int*   qz_o = (const int*)d_in[15];
    const float* sc_o = (const float*)d_in[16];
    float* out = (float*)d_out;

    float *Wqh,*Wql,*Wkh,*Wkl,*Wvh,*Wvl,*Woh,*Wol,*Xh,*Xl,*Qb,*Kb,*Vb,*Obh,*Obl;
    cudaGetSymbolAddress((void**)&Wqh, g_Wq_h); cudaGetSymbolAddress((void**)&Wql, g_Wq_l);
    cudaGetSymbolAddress((void**)&Wkh, g_Wk_h); cudaGetSymbolAddress((void**)&Wkl, g_Wk_l);
    cudaGetSymbolAddress((void**)&Wvh, g_Wv_h); cudaGetSymbolAddress((void**)&Wvl, g_Wv_l);
    cudaGetSymbolAddress((void**)&Woh, g_Wo_h); cudaGetSymbolAddress((void**)&Wol, g_Wo_l);
    cudaGetSymbolAddress((void**)&Xh,  g_X_h);  cudaGetSymbolAddress((void**)&Xl,  g_X_l);
    cudaGetSymbolAddress((void**)&Qb,  g_Q);
    cudaGetSymbolAddress((void**)&Kb,  g_K);
    cudaGetSymbolAddress((void**)&Vb,  g_V);
    cudaGetSymbolAddress((void**)&Obh, g_Ob_h); cudaGetSymbolAddress((void**)&Obl, g_Ob_l);

    cudaFuncSetAttribute(gemm3t<true>,  cudaFuncAttributeMaxDynamicSharedMemorySize, GEMM_SMEM);
    cudaFuncSetAttribute(gemm3t<false>, cudaFuncAttributeMaxDynamicSharedMemorySize, GEMM_SMEM);
    cudaFuncSetAttribute(attn_tc, cudaFuncAttributeMaxDynamicSharedMemorySize, ATTN_SMEM_BYTES);

    // dequant weights -> hi/lo
    {
        int cnt_big = HID * (DQ / 8);
        int cnt_kv  = HID * (DKV / 8);
        dequant_kernel<<<(cnt_big + 255) / 256, 256>>>(qw_q, qz_q, sc_q, Wqh, Wql, HID, DQ);
        dequant_kernel<<<(cnt_kv  + 255) / 256, 256>>>(qw_k, qz_k, sc_k, Wkh, Wkl, HID, DKV);
        dequant_kernel<<<(cnt_kv  + 255) / 256, 256>>>(qw_v, qz_v, sc_v, Wvh, Wvl, HID, DKV);
        dequant_kernel<<<(cnt_big + 255) / 256, 256>>>(qw_o, qz_o, sc_o, Woh, Wol, DQ, HID);
    }

    // split activations
    {
        int n = SEQ * HID;
        split_kernel<<<(n + 255) / 256, 256>>>(x, Xh, Xl, n);
    }

    // projections (+bias), fp32-accurate via 3xTF32
    gemm3t<true><<<dim3(DQ / BN, SEQ / BM), 256, GEMM_SMEM>>>(Xh, Xl, Wqh, Wql, b_q, Qb, SEQ, DQ, HID);
    gemm3t<true><<<dim3(DKV / BN, SEQ / BM), 256, GEMM_SMEM>>>(Xh, Xl, Wkh, Wkl, b_k, Kb, SEQ, DKV, HID);
    gemm3t<true><<<dim3(DKV / BN, SEQ / BM), 256, GEMM_SMEM>>>(Xh, Xl, Wvh, Wvl, b_v, Vb, SEQ, DKV, HID);

    // RoPE
    {
        int total = SEQ * (NH + NKV) * (HD / 2);
        rope_kernel<<<(total + 255) / 256, 256>>>(Qb, Kb, pos);
    }

    // attention (writes hi/lo split output)
    attn_tc<<<dim3(SEQ / QB, NH), 256, ATTN_SMEM_BYTES>>>(Qb, Kb, Vb, Obh, Obl);

    // output projection straight into d_out
    gemm3t<false><<<dim3(HID / BN, SEQ / BM), 256, GEMM_SMEM>>>(Obh, Obl, Woh, Wol, nullptr, out, SEQ, HID, DQ);
}

// round 6
// speedup vs baseline: 2.8499x; 1.8661x over previous
#include <cuda_runtime.h>
#include <cuda_bf16.h>
#include <cstdint>
#include <cstddef>

// ---------------- problem constants ----------------
#define HID   3584
#define NH    28
#define NKV   4
#define HD    128
#define SEQ   2048
#define DQ    (NH*HD)     // 3584
#define DKV   (NKV*HD)    // 512
#define GRP   128

// ---------------- device scratch ----------------
// transposed bf16 weights: Wt[n][k], hi/lo split
__device__ __nv_bfloat16 g_WqT_h[(size_t)DQ * HID],  g_WqT_l[(size_t)DQ * HID];
__device__ __nv_bfloat16 g_WkT_h[(size_t)DKV * HID], g_WkT_l[(size_t)DKV * HID];
__device__ __nv_bfloat16 g_WvT_h[(size_t)DKV * HID], g_WvT_l[(size_t)DKV * HID];
__device__ __nv_bfloat16 g_WoT_h[(size_t)HID * DQ],  g_WoT_l[(size_t)HID * DQ];
// activations bf16 hi/lo
__device__ __nv_bfloat16 g_Xh[SEQ * HID], g_Xl[SEQ * HID];
// fp32 intermediates
__device__ float g_Q[SEQ * DQ];
__device__ float g_K[SEQ * DKV];
__device__ float g_V[SEQ * DKV];
// attention output bf16 hi/lo
__device__ __nv_bfloat16 g_Obh[SEQ * DQ], g_Obl[SEQ * DQ];

// ---------------- helpers ----------------
__device__ __forceinline__ float f2tff(float x) {
    unsigned u;
    asm("cvt.rna.tf32.f32 %0, %1;" : "=r"(u) : "f"(x));
    return __uint_as_float(u);
}

__device__ __forceinline__ unsigned sptr(const void* p) {
    return (unsigned)__cvta_generic_to_shared(p);
}

#define CP_ASYNC16(dst, src) \
    asm volatile("cp.async.cg.shared.global [%0], [%1], 16;\n" :: "r"(dst), "l"(src))
#define CP_COMMIT() asm volatile("cp.async.commit_group;\n")

#define MMA_TF32(C, Aa, Bb) \
    asm volatile("mma.sync.aligned.m16n8k8.row.col.f32.tf32.tf32.f32 " \
        "{%0,%1,%2,%3},{%4,%5,%6,%7},{%8,%9},{%0,%1,%2,%3};" \
        : "+f"(C[0]), "+f"(C[1]), "+f"(C[2]), "+f"(C[3]) \
        : "r"(Aa[0]), "r"(Aa[1]), "r"(Aa[2]), "r"(Aa[3]), "r"(Bb[0]), "r"(Bb[1]))

#define MMA_BF16(C, Aa, Bb) \
    asm volatile("mma.sync.aligned.m16n8k16.row.col.f32.bf16.bf16.f32 " \
        "{%0,%1,%2,%3},{%4,%5,%6,%7},{%8,%9},{%0,%1,%2,%3};" \
        : "+f"(C[0]), "+f"(C[1]), "+f"(C[2]), "+f"(C[3]) \
        : "r"(Aa[0]), "r"(Aa[1]), "r"(Aa[2]), "r"(Aa[3]), "r"(Bb[0]), "r"(Bb[1]))

__device__ __forceinline__ void bsplit(float v, __nv_bfloat16& h, __nv_bfloat16& l) {
    h = __float2bfloat16_rn(v);
    l = __float2bfloat16_rn(v - __bfloat162float(h));
}

// ---------------- AWQ dequant -> transposed bf16 hi/lo Wt[n][k] ----------------
// thread handles (n, kblk): 8 consecutive k for one output column n.
__global__ void dequantT_kernel(const int* __restrict__ qw, const int* __restrict__ qz,
                                const float* __restrict__ sc,
                                __nv_bfloat16* __restrict__ Wh,
                                __nv_bfloat16* __restrict__ Wl,
                                int din, int dout) {
    int idx = blockIdx.x * blockDim.x + threadIdx.x;
    int total = dout * (din >> 3);
    if (idx >= total) return;
    int n    = idx % dout;      // consecutive tid -> consecutive n
    int kblk = idx / dout;
    int dout8 = dout >> 3;
    int pcol = n >> 3;
    int shift = (n & 7) * 4;
    int grp = (kblk * 8) >> 7;  // same group for all 8 k (8 | 128)
    int z = (qz[(size_t)grp * dout8 + pcol] >> shift) & 0xF;
    float s = sc[(size_t)grp * dout + n];
    __nv_bfloat16 hv[8], lv[8];
#pragma unroll
    for (int j = 0; j < 8; j++) {
        int k = kblk * 8 + j;
        int w = (qw[(size_t)k * dout8 + pcol] >> shift) & 0xF;
        float v = (float)(w - z) * s;
        bsplit(v, hv[j], lv[j]);
    }
    size_t off = (size_t)n * din + kblk * 8;
    *(float4*)&Wh[off] = *(float4*)hv;
    *(float4*)&Wl[off] = *(float4*)lv;
}

// ---------------- split fp32 activations -> bf16 hi/lo ----------------
__global__ void splitb_kernel(const float* __restrict__ in,
                              __nv_bfloat16* __restrict__ hi,
                              __nv_bfloat16* __restrict__ lo, int n) {
    int i = blockIdx.x * blockDim.x + threadIdx.x;
    if (i < n) {
        __nv_bfloat16 h, l;
        bsplit(in[i], h, l);
        hi[i] = h;
        lo[i] = l;
    }
}

// ---------------- bf16x2-split tensor-core GEMM ----------------
// C[M,N] = A[M,K] @ Bt[N,K]^T (+bias). A/Bt given as bf16 hi/lo arrays.
// 128x128x32 tile, 256 thr (8 warps 2x4), warp tile 64x32, mma m16n8k16,
// 3 products per k16: hh + hl + lh. 2-stage cp.async.
#define BSTRW 20                 // smem row stride in 32-bit words (40 bf16)
#define TW (128*BSTRW)           // words per array per stage = 2560
#define BSTAGE (4*TW)            // Ah|Al|Bh|Bl per stage = 10240 words
#define BGEMM_SMEM (2*BSTAGE*4)  // 81920 bytes

template <bool HAS_BIAS>
__global__ __launch_bounds__(256) void gemmb(const __nv_bfloat16* __restrict__ Ah,
                                             const __nv_bfloat16* __restrict__ Al,
                                             const __nv_bfloat16* __restrict__ Bth,
                                             const __nv_bfloat16* __restrict__ Btl,
                                             const float* __restrict__ bias,
                                             float* __restrict__ C,
                                             int M, int N, int K) {
    extern __shared__ unsigned smu[];
    int tid  = threadIdx.x;
    int lane = tid & 31;
    int wid  = tid >> 5;
    int gid  = lane >> 2, tig = lane & 3;
    int warp_m = wid >> 2;   // 0..1
    int warp_n = wid & 3;    // 0..3

    int srow = tid >> 1;           // 0..127
    int soff = (tid & 1) * 8;      // word offset within row (0 / 8)
    size_t agoff = (size_t)(blockIdx.y * 128 + srow) * K + (tid & 1) * 16;
    size_t bgoff = (size_t)(blockIdx.x * 128 + srow) * K + (tid & 1) * 16;
    unsigned smbase = sptr(smu);

    float acc[4][4][4];
#pragma unroll
    for (int mt = 0; mt < 4; mt++)
#pragma unroll
        for (int nt = 0; nt < 4; nt++)
#pragma unroll
            for (int i = 0; i < 4; i++) acc[mt][nt][i] = 0.f;

    const int NT = K / 32;

#define GISSUE(kt, stage) do {                                               \
        unsigned d0 = smbase + ((stage) * BSTAGE + srow * BSTRW + soff) * 4; \
        const __nv_bfloat16* pah = Ah  + agoff + (size_t)(kt) * 32;          \
        const __nv_bfloat16* pal = Al  + agoff + (size_t)(kt) * 32;          \
        const __nv_bfloat16* pbh = Bth + bgoff + (size_t)(kt) * 32;          \
        const __nv_bfloat16* pbl = Btl + bgoff + (size_t)(kt) * 32;         \
        CP_ASYNC16(d0,              pah); CP_ASYNC16(d0 + 16,              pah + 8); \
        CP_ASYNC16(d0 + TW*4,       pal); CP_ASYNC16(d0 + TW*4 + 16,       pal + 8); \
        CP_ASYNC16(d0 + 2*TW*4,     pbh); CP_ASYNC16(d0 + 2*TW*4 + 16,     pbh + 8); \
        CP_ASYNC16(d0 + 3*TW*4,     pbl); CP_ASYNC16(d0 + 3*TW*4 + 16,     pbl + 8); \
        CP_COMMIT();                                                         \
    } while (0)

    GISSUE(0, 0);

    for (int kt = 0; kt < NT; kt++) {
        int cur = kt & 1;
        if (kt + 1 < NT) {
            GISSUE(kt + 1, 1 - cur);
            asm volatile("cp.async.wait_group 1;\n");
        } else {
            asm volatile("cp.async.wait_group 0;\n");
        }
        __syncthreads();

        const unsigned* SAh = smu + cur * BSTAGE;
        const unsigned* SAl = SAh + TW;
        const unsigned* SBh = SAh + 2 * TW;
        const unsigned* SBl = SAh + 3 * TW;

#pragma unroll
        for (int ks = 0; ks < 2; ks++) {
            int ko = ks * 8;
            unsigned bh[4][2], bl[4][2];
#pragma unroll
            for (int nt = 0; nt < 4; nt++) {
                int nb = (warp_n * 32 + nt * 8 + gid) * BSTRW + ko + tig;
                bh[nt][0] = SBh[nb]; bh[nt][1] = SBh[nb + 4];
                bl[nt][0] = SBl[nb]; bl[nt][1] = SBl[nb + 4];
            }
#pragma unroll
            for (int mt = 0; mt < 4; mt++) {
                int ab = (warp_m * 64 + mt * 16 + gid) * BSTRW + ko + tig;
                unsigned ah[4] = { SAh[ab], SAh[ab + 8*BSTRW], SAh[ab + 4], SAh[ab + 8*BSTRW + 4] };
                unsigned al[4] = { SAl[ab], SAl[ab + 8*BSTRW], SAl[ab + 4], SAl[ab + 8*BSTRW + 4] };
#pragma unroll
                for (int nt = 0; nt < 4; nt++) {
                    MMA_BF16(acc[mt][nt], ah, bh[nt]);
                    MMA_BF16(acc[mt][nt], ah, bl[nt]);
                    MMA_BF16(acc[mt][nt], al, bh[nt]);
                }
            }
        }
        __syncthreads();
    }

    // epilogue
#pragma unroll
    for (int mt = 0; mt < 4; mt++) {
        int row = blockIdx.y * 128 + warp_m * 64 + mt * 16 + gid;
#pragma unroll
        for (int nt = 0; nt < 4; nt++) {
            int col = blockIdx.x * 128 + warp_n * 32 + nt * 8 + tig * 2;
            float b0 = 0.f, b1 = 0.f;
            if (HAS_BIAS) { b0 = bias[col]; b1 = bias[col + 1]; }
            float2 v0 = { acc[mt][nt][0] + b0, acc[mt][nt][1] + b1 };
            float2 v1 = { acc[mt][nt][2] + b0, acc[mt][nt][3] + b1 };
            *(float2*)&C[(size_t)row * N + col]       = v0;
            *(float2*)&C[(size_t)(row + 8) * N + col] = v1;
        }
    }
#undef GISSUE
}

// ---------------- RoPE (fp32, in-place) ----------------
__global__ void rope_kernel(float* __restrict__ Q, float* __restrict__ K,
                            const int* __restrict__ pos) {
    int idx = blockIdx.x * blockDim.x + threadIdx.x;
    const int total = SEQ * (NH + NKV) * (HD / 2);
    if (idx >= total) return;
    int d = idx & 63;
    int h = (idx >> 6) & 31;
    int s = idx >> 11;
    float inv = expf((float)d * (-13.815510557964274f / 64.0f));
    float ang = (float)pos[s] * inv;
    float si, co;
    sincosf(ang, &si, &co);
    float* p;
    if (h < NH) p = Q + (size_t)s * DQ + h * HD;
    else        p = K + (size_t)s * DKV + (h - NH) * HD;
    float x0 = p[d];
    float x1 = p[d + 64];
    p[d]      = x0 * co - x1 * si;
    p[d + 64] = x1 * co + x0 * si;
}

// ---------------- 3xTF32 causal GQA flash attention ----------------
#define QB   64
#define QSTR 132
#define SSTR 68

#define A_QH 0
#define A_QL (A_QH + QB*QSTR)
#define A_KH (A_QL + QB*QSTR)
#define A_KL (A_KH + QB*QSTR)
#define A_SS (A_KL + QB*QSTR)
#define A_SL (A_SS + QB*SSTR)
#define A_RM (A_SL + QB*SSTR)
#define ATTN_SMEM_FLOATS (A_RM + 3*QB)
#define ATTN_SMEM_BYTES  (ATTN_SMEM_FLOATS * 4)

__global__ __launch_bounds__(256) void attn_tc(const float* __restrict__ Q,
                                               const float* __restrict__ K,
                                               const float* __restrict__ V,
                                               __nv_bfloat16* __restrict__ Oh,
                                               __nv_bfloat16* __restrict__ Ol) {
    extern __shared__ float sm[];
    float* Qh = sm + A_QH;
    float* Ql = sm + A_QL;
    float* KVh = sm + A_KH;
    float* KVl = sm + A_KL;
    float* Ss = sm + A_SS;
    float* Sl = sm + A_SL;
    float* rowM = sm + A_RM;
    float* rowL = rowM + QB;
    float* rowC = rowL + QB;
    const unsigned* QhU = (const unsigned*)Qh;
    const unsigned* QlU = (const unsigned*)Ql;
    const unsigned* KVhU = (const unsigned*)KVh;
    const unsigned* KVlU = (const unsigned*)KVl;
    const unsigned* SsU = (const unsigned*)Ss;
    const unsigned* SlU = (const unsigned*)Sl;

    int qb = (int)gridDim.x - 1 - (int)blockIdx.x;   // heavy blocks first
    int h  = blockIdx.y;
    int hk = h / (NH / NKV);
    int tid  = threadIdx.x;
    int lane = tid & 31;
    int wid  = tid >> 5;
    int gid  = lane >> 2, tig = lane & 3;
    int warp_m = wid >> 2;
    int warp_n = wid & 3;

    // load + split Q tile
#pragma unroll
    for (int j = 0; j < 8; j++) {
        int idx = tid + 256 * j;
        int r  = idx >> 5;
        int c4 = (idx & 31) << 2;
        float4 v = *(const float4*)&Q[(size_t)(qb * QB + r) * DQ + h * HD + c4];
        float4 hh = { f2tff(v.x), f2tff(v.y), f2tff(v.z), f2tff(v.w) };
        float4 ll = { f2tff(v.x - hh.x), f2tff(v.y - hh.y),
                      f2tff(v.z - hh.z), f2tff(v.w - hh.w) };
        *(float4*)&Qh[r * QSTR + c4] = hh;
        *(float4*)&Ql[r * QSTR + c4] = ll;
    }
    if (tid < QB) { rowM[tid] = -1e30f; rowL[tid] = 0.f; }

    float oacc[2][4][4];
#pragma unroll
    for (int mt = 0; mt < 2; mt++)
#pragma unroll
        for (int nt = 0; nt < 4; nt++)
#pragma unroll
            for (int i = 0; i < 4; i++) oacc[mt][nt][i] = 0.f;

    const float scale = 0.08838834764831845f;

    for (int kb = 0; kb <= qb; kb++) {
        __syncthreads();
        // load + split K tile
#pragma unroll
        for (int j = 0; j < 8; j++) {
            int idx = tid + 256 * j;
            int r  = idx >> 5;
            int c4 = (idx & 31) << 2;
            float4 v = *(const float4*)&K[(size_t)(kb * QB + r) * DKV + hk * HD + c4];
            float4 hh = { f2tff(v.x), f2tff(v.y), f2tff(v.z), f2tff(v.w) };
            float4 ll = { f2tff(v.x - hh.x), f2tff(v.y - hh.y),
                          f2tff(v.z - hh.z), f2tff(v.w - hh.w) };
            *(float4*)&KVh[r * QSTR + c4] = hh;
            *(float4*)&KVl[r * QSTR + c4] = ll;
        }
        __syncthreads();

        // ---- S = Q @ K^T (3xTF32), warp tile 32x16 ----
        float sacc[2][2][4];
#pragma unroll
        for (int mt = 0; mt < 2; mt++)
#pragma unroll
            for (int nt = 0; nt < 2; nt++)
#pragma unroll
                for (int i = 0; i < 4; i++) sacc[mt][nt][i] = 0.f;

#pragma unroll
        for (int ks = 0; ks < 16; ks++) {
            int kk = ks * 8;
            unsigned ah[2][4], al[2][4], bh[2][2], bl[2][2];
#pragma unroll
            for (int mt = 0; mt < 2; mt++) {
                int o = (warp_m * 32 + mt * 16 + gid) * QSTR + kk + tig;
                ah[mt][0] = QhU[o];     ah[mt][1] = QhU[o + 8 * QSTR];
                ah[mt][2] = QhU[o + 4]; ah[mt][3] = QhU[o + 8 * QSTR + 4];
                al[mt][0] = QlU[o];     al[mt][1] = QlU[o + 8 * QSTR];
                al[mt][2] = QlU[o + 4]; al[mt][3] = QlU[o + 8 * QSTR + 4];
            }
#pragma unroll
            for (int nt = 0; nt < 2; nt++) {
                int o = (warp_n * 16 + nt * 8 + gid) * QSTR + kk + tig;
                bh[nt][0] = KVhU[o]; bh[nt][1] = KVhU[o + 4];
                bl[nt][0] = KVlU[o]; bl[nt][1] = KVlU[o + 4];
            }
#pragma unroll
            for (int mt = 0; mt < 2; mt++)
#pragma unroll
                for (int nt = 0; nt < 2; nt++) {
                    MMA_TF32(sacc[mt][nt], ah[mt], bh[nt]);
                    MMA_TF32(sacc[mt][nt], ah[mt], bl[nt]);
                    MMA_TF32(sacc[mt][nt], al[mt], bh[nt]);
                }
        }

        bool diag = (kb == qb);
#pragma unroll
        for (int mt = 0; mt < 2; mt++) {
            int r0 = warp_m * 32 + mt * 16 + gid;
#pragma unroll
            for (int nt = 0; nt < 2; nt++) {
                int c0 = warp_n * 16 + nt * 8 + tig * 2;
                float v00 = sacc[mt][nt][0] * scale;
                float v01 = sacc[mt][nt][1] * scale;
                float v10 = sacc[mt][nt][2] * scale;
                float v11 = sacc[mt][nt][3] * scale;
                if (diag) {
                    if (c0     > r0)     v00 = -1e30f;
                    if (c0 + 1 > r0)     v01 = -1e30f;
                    if (c0     > r0 + 8) v10 = -1e30f;
                    if (c0 + 1 > r0 + 8) v11 = -1e30f;
                }
                Ss[r0 * SSTR + c0]           = v00;
                Ss[r0 * SSTR + c0 + 1]       = v01;
                Ss[(r0 + 8) * SSTR + c0]     = v10;
                Ss[(r0 + 8) * SSTR + c0 + 1] = v11;
            }
        }
        __syncthreads();

        // ---- load + split V tile (overwrites K buffer; K fully consumed) ----
#pragma unroll
        for (int j = 0; j < 8; j++) {
            int idx = tid + 256 * j;
            int r  = idx >> 5;
            int c4 = (idx & 31) << 2;
            float4 v = *(const float4*)&V[(size_t)(kb * QB + r) * DKV + hk * HD + c4];
            float4 hh = { f2tff(v.x), f2tff(v.y), f2tff(v.z), f2tff(v.w) };
            float4 ll = { f2tff(v.x - hh.x), f2tff(v.y - hh.y),
                          f2tff(v.z - hh.z), f2tff(v.w - hh.w) };
            *(float4*)&KVh[r * QSTR + c4] = hh;
            *(float4*)&KVl[r * QSTR + c4] = ll;
        }

        // ---- online softmax: 4 lanes per row ----
        {
            int r = tid >> 2, sub = tid & 3;
            float mOld = rowM[r];
            float mx = mOld;
#pragma unroll
            for (int jj = 0; jj < 16; jj++)
                mx = fmaxf(mx, Ss[r * SSTR + sub * 16 + jj]);
            mx = fmaxf(mx, __shfl_xor_sync(0xffffffffu, mx, 1));
            mx = fmaxf(mx, __shfl_xor_sync(0xffffffffu, mx, 2));
            float l = 0.f;
#pragma unroll
            for (int jj = 0; jj < 16; jj++) {
                int j = sub * 16 + jj;
                float p = __expf(Ss[r * SSTR + j] - mx);
                float ph = f2tff(p);
                Ss[r * SSTR + j] = ph;
                Sl[r * SSTR + j] = f2tff(p - ph);
                l += p;
            }
            l += __shfl_xor_sync(0xffffffffu, l, 1);
            l += __shfl_xor_sync(0xffffffffu, l, 2);
            if (sub == 0) {
                float corr = __expf(mOld - mx);
                rowL[r] = rowL[r] * corr + l;
                rowM[r] = mx;
                rowC[r] = corr;
            }
        }
        __syncthreads();

        // ---- rescale O, then O += P @ V (3xTF32), warp tile 32x32 ----
#pragma unroll
        for (int mt = 0; mt < 2; mt++) {
            float cr0 = rowC[warp_m * 32 + mt * 16 + gid];
            float cr1 = rowC[warp_m * 32 + mt * 16 + gid + 8];
#pragma unroll
            for (int nt = 0; nt < 4; nt++) {
                oacc[mt][nt][0] *= cr0; oacc[mt][nt][1] *= cr0;
                oacc[mt][nt][2] *= cr1; oacc[mt][nt][3] *= cr1;
            }
        }
#pragma unroll
        for (int ks = 0; ks < 8; ks++) {
            int kk = ks * 8;
            unsigned ah[2][4], al[2][4], bh[4][2], bl[4][2];
#pragma unroll
            for (int mt = 0; mt < 2; mt++) {
                int o = (warp_m * 32 + mt * 16 + gid) * SSTR + kk + tig;
                ah[mt][0] = SsU[o];     ah[mt][1] = SsU[o + 8 * SSTR];
                ah[mt][2] = SsU[o + 4]; ah[mt][3] = SsU[o + 8 * SSTR + 4];
                al[mt][0] = SlU[o];     al[mt][1] = SlU[o + 8 * SSTR];
                al[mt][2] = SlU[o + 4]; al[mt][3] = SlU[o + 8 * SSTR + 4];
            }
#pragma unroll
            for (int nt = 0; nt < 4; nt++) {
                int o = (kk + tig) * QSTR + warp_n * 32 + nt * 8 + gid;
                bh[nt][0] = KVhU[o]; bh[nt][1] = KVhU[o + 4 * QSTR];
                bl[nt][0] = KVlU[o]; bl[nt][1] = KVlU[o + 4 * QSTR];
            }
#pragma unroll
            for (int mt = 0; mt < 2; mt++)
#pragma unroll
                for (int nt = 0; nt < 4; nt++) {
                    MMA_TF32(oacc[mt][nt], ah[mt], bh[nt]);
                    MMA_TF32(oacc[mt][nt], ah[mt], bl[nt]);
                    MMA_TF32(oacc[mt][nt], al[mt], bh[nt]);
                }
        }
    }

    // finalize: divide by l, write bf16 hi/lo split (feeds O-projection)
#pragma unroll
    for (int mt = 0; mt < 2; mt++) {
        int r0 = warp_m * 32 + mt * 16 + gid;
        float inv0 = 1.0f / rowL[r0];
        float inv1 = 1.0f / rowL[r0 + 8];
        int gr = qb * QB + r0;
#pragma unroll
        for (int nt = 0; nt < 4; nt++) {
            int c = h * HD + warp_n * 32 + nt * 8 + tig * 2;
            float o00 = oacc[mt][nt][0] * inv0, o01 = oacc[mt][nt][1] * inv0;
            float o10 = oacc[mt][nt][2] * inv1, o11 = oacc[mt][nt][3] * inv1;
            __nv_bfloat16 h00, h01, h10, h11, l00, l01, l10, l11;
            bsplit(o00, h00, l00); bsplit(o01, h01, l01);
            bsplit(o10, h10, l10); bsplit(o11, h11, l11);
            __nv_bfloat162 ph0, ph1, pl0, pl1;
            ph0.x = h00; ph0.y = h01;  ph1.x = h10; ph1.y = h11;
            pl0.x = l00; pl0.y = l01;  pl1.x = l10; pl1.y = l11;
            *(__nv_bfloat162*)&Oh[(size_t)gr * DQ + c]       = ph0;
            *(__nv_bfloat162*)&Oh[(size_t)(gr + 8) * DQ + c] = ph1;
            *(__nv_bfloat162*)&Ol[(size_t)gr * DQ + c]       = pl0;
            *(__nv_bfloat162*)&Ol[(size_t)(gr + 8) * DQ + c] = pl1;
        }
    }
}

// ---------------- launch ----------------
extern "C" void kernel_launch(void* const* d_in, const int* in_sizes, int n_in,
                              void* d_out, int out_size) {
    const float* x    = (const float*)d_in[0];
    const int*   pos  = (const int*)d_in[1];
    const int*   qw_q = (const int*)d_in[2];
    const int*   qz_q = (const int*)d_in[3];
    const float* sc_q = (const float*)d_in[4];
    const float* b_q  = (const float*)d_in[5];
    const int*   qw_k = (const int*)d_in[6];
    const int*   qz_k = (const int*)d_in[7];
    const float* sc_k = (const float*)d_in[8];
    const float* b_k  = (const float*)d_in[9];
    const int*   qw_v = (const int*)d_in[10];
    const int*   qz_v = (const int*)d_in[11];
    const float* sc_v = (const float*)d_in[12];
    const float* b_v  = (const float*)d_in[13];
    const int*   qw_o = (const int*)d_in[14];
    const int*   qz_o = (const int*)d_in[15];
    const float* sc_o = (const float*)d_in[16];
    float* out = (float*)d_out;

    __nv_bfloat16 *WqTh,*WqTl,*WkTh,*WkTl,*WvTh,*WvTl,*WoTh,*WoTl,*Xh,*Xl,*Obh,*Obl;
    float *Qb,*Kb,*Vb;
    cudaGetSymbolAddress((void**)&WqTh, g_WqT_h); cudaGetSymbolAddress((void**)&WqTl, g_WqT_l);
    cudaGetSymbolAddress((void**)&WkTh, g_WkT_h); cudaGetSymbolAddress((void**)&WkTl, g_WkT_l);
    cudaGetSymbolAddress((void**)&WvTh, g_WvT_h); cudaGetSymbolAddress((void**)&WvTl, g_WvT_l);
    cudaGetSymbolAddress((void**)&WoTh, g_WoT_h); cudaGetSymbolAddress((void**)&WoTl, g_WoT_l);
    cudaGetSymbolAddress((void**)&Xh, g_Xh);      cudaGetSymbolAddress((void**)&Xl, g_Xl);
    cudaGetSymbolAddress((void**)&Obh, g_Obh);    cudaGetSymbolAddress((void**)&Obl, g_Obl);
    cudaGetSymbolAddress((void**)&Qb, g_Q);
    cudaGetSymbolAddress((void**)&Kb, g_K);
    cudaGetSymbolAddress((void**)&Vb, g_V);

    cudaFuncSetAttribute(gemmb<true>,  cudaFuncAttributeMaxDynamicSharedMemorySize, BGEMM_SMEM);
    cudaFuncSetAttribute(gemmb<false>, cudaFuncAttributeMaxDynamicSharedMemorySize, BGEMM_SMEM);
    cudaFuncSetAttribute(attn_tc, cudaFuncAttributeMaxDynamicSharedMemorySize, ATTN_SMEM_BYTES);

    // dequant -> transposed bf16 hi/lo weights
    {
        int t_q = DQ  * (HID / 8);   // 1,605,632
        int t_kv = DKV * (HID / 8);  // 229,376
        int t_o = HID * (DQ / 8);    // 1,605,632
        dequantT_kernel<<<(t_q  + 255) / 256, 256>>>(qw_q, qz_q, sc_q, WqTh, WqTl, HID, DQ);
        dequantT_kernel<<<(t_kv + 255) / 256, 256>>>(qw_k, qz_k, sc_k, WkTh, WkTl, HID, DKV);
        dequantT_kernel<<<(t_kv + 255) / 256, 256>>>(qw_v, qz_v, sc_v, WvTh, WvTl, HID, DKV);
        dequantT_kernel<<<(t_o  + 255) / 256, 256>>>(qw_o, qz_o, sc_o, WoTh, WoTl, DQ, HID);
    }

    // split activations to bf16 hi/lo
    {
        int n = SEQ * HID;
        splitb_kernel<<<(n + 255) / 256, 256>>>(x, Xh, Xl, n);
    }

    // projections (+bias), bf16x2-split MMAs
    gemmb<true><<<dim3(DQ / 128, SEQ / 128), 256, BGEMM_SMEM>>>(Xh, Xl, WqTh, WqTl, b_q, Qb, SEQ, DQ, HID);
    gemmb<true><<<dim3(DKV / 128, SEQ / 128), 256, BGEMM_SMEM>>>(Xh, Xl, WkTh, WkTl, b_k, Kb, SEQ, DKV, HID);
    gemmb<true><<<dim3(DKV / 128, SEQ / 128), 256, BGEMM_SMEM>>>(Xh, Xl, WvTh, WvTl, b_v, Vb, SEQ, DKV, HID);

    // RoPE
    {
        int total = SEQ * (NH + NKV) * (HD / 2);
        rope_kernel<<<(total + 255) / 256, 256>>>(Qb, Kb, pos);
    }

    // attention (3xTF32), outputs bf16 hi/lo split
    attn_tc<<<dim3(SEQ / QB, NH), 256, ATTN_SMEM_BYTES>>>(Qb, Kb, Vb, Obh, Obl);

    // output projection straight into d_out
    gemmb<false><<<dim3(HID / 128, SEQ / 128), 256, BGEMM_SMEM>>>(Obh, Obl, WoTh, WoTl, nullptr, out, SEQ, HID, DQ);
}

// round 7
// speedup vs baseline: 3.2620x; 1.1446x over previous
#include <cuda_runtime.h>
#include <cuda_bf16.h>
#include <cstdint>
#include <cstddef>
#include <cstring>

// ---------------- problem constants ----------------
#define HID   3584
#define NH    28
#define NKV   4
#define HD    128
#define SEQ   2048
#define DQ    (NH*HD)     // 3584
#define DKV   (NKV*HD)    // 512
#define GRP   128

// ---------------- device scratch ----------------
// transposed bf16 weights: Wt[n][k], hi/lo split
__device__ __nv_bfloat16 g_WqT_h[(size_t)DQ * HID],  g_WqT_l[(size_t)DQ * HID];
__device__ __nv_bfloat16 g_WkT_h[(size_t)DKV * HID], g_WkT_l[(size_t)DKV * HID];
__device__ __nv_bfloat16 g_WvT_h[(size_t)DKV * HID], g_WvT_l[(size_t)DKV * HID];
__device__ __nv_bfloat16 g_WoT_h[(size_t)HID * DQ],  g_WoT_l[(size_t)HID * DQ];
// activations bf16 hi/lo
__device__ __nv_bfloat16 g_Xh[SEQ * HID], g_Xl[SEQ * HID];
// fp32 projection outputs
__device__ float g_Q[SEQ * DQ];
__device__ float g_K[SEQ * DKV];
__device__ float g_V[SEQ * DKV];
// attention inputs, bf16 hi/lo (Q/K after rope; V transposed per head: [DKV][SEQ])
__device__ __nv_bfloat16 g_Qbh[SEQ * DQ],  g_Qbl[SEQ * DQ];
__device__ __nv_bfloat16 g_Kbh[SEQ * DKV], g_Kbl[SEQ * DKV];
__device__ __nv_bfloat16 g_Vth[(size_t)DKV * SEQ], g_Vtl[(size_t)DKV * SEQ];
// attention output bf16 hi/lo
__device__ __nv_bfloat16 g_Obh[SEQ * DQ], g_Obl[SEQ * DQ];

// ---------------- helpers ----------------
__device__ __forceinline__ unsigned sptr(const void* p) {
    return (unsigned)__cvta_generic_to_shared(p);
}

#define CP_ASYNC16(dst, src) \
    asm volatile("cp.async.cg.shared.global [%0], [%1], 16;\n" :: "r"(dst), "l"(src))
#define CP_COMMIT() asm volatile("cp.async.commit_group;\n")

#define MMA_BF16(C, Aa, Bb) \
    asm volatile("mma.sync.aligned.m16n8k16.row.col.f32.bf16.bf16.f32 " \
        "{%0,%1,%2,%3},{%4,%5,%6,%7},{%8,%9},{%0,%1,%2,%3};" \
        : "+f"(C[0]), "+f"(C[1]), "+f"(C[2]), "+f"(C[3]) \
        : "r"(Aa[0]), "r"(Aa[1]), "r"(Aa[2]), "r"(Aa[3]), "r"(Bb[0]), "r"(Bb[1]))

__device__ __forceinline__ void bsplit(float v, __nv_bfloat16& h, __nv_bfloat16& l) {
    h = __float2bfloat16_rn(v);
    l = __float2bfloat16_rn(v - __bfloat162float(h));
}

// ---------------- AWQ dequant -> transposed bf16 hi/lo Wt[n][k] ----------------
__global__ void dequantT_kernel(const int* __restrict__ qw, const int* __restrict__ qz,
                                const float* __restrict__ sc,
                                __nv_bfloat16* __restrict__ Wh,
                                __nv_bfloat16* __restrict__ Wl,
                                int din, int dout) {
    int idx = blockIdx.x * blockDim.x + threadIdx.x;
    int total = dout * (din >> 3);
    if (idx >= total) return;
    int n    = idx % dout;
    int kblk = idx / dout;
    int dout8 = dout >> 3;
    int pcol = n >> 3;
    int shift = (n & 7) * 4;
    int grp = (kblk * 8) >> 7;
    int z = (qz[(size_t)grp * dout8 + pcol] >> shift) & 0xF;
    float s = sc[(size_t)grp * dout + n];
    __nv_bfloat16 hv[8], lv[8];
#pragma unroll
    for (int j = 0; j < 8; j++) {
        int k = kblk * 8 + j;
        int w = (qw[(size_t)k * dout8 + pcol] >> shift) & 0xF;
        float v = (float)(w - z) * s;
        bsplit(v, hv[j], lv[j]);
    }
    size_t off = (size_t)n * din + kblk * 8;
    *(float4*)&Wh[off] = *(float4*)hv;
    *(float4*)&Wl[off] = *(float4*)lv;
}

// ---------------- split fp32 -> bf16 hi/lo ----------------
__global__ void splitb_kernel(const float* __restrict__ in,
                              __nv_bfloat16* __restrict__ hi,
                              __nv_bfloat16* __restrict__ lo, int n) {
    int i = blockIdx.x * blockDim.x + threadIdx.x;
    if (i < n) {
        __nv_bfloat16 h, l;
        bsplit(in[i], h, l);
        hi[i] = h;
        lo[i] = l;
    }
}

// ---------------- bf16x2-split tensor-core GEMM (proven in R6) ----------------
#define BSTRW 20
#define TW (128*BSTRW)
#define BSTAGE (4*TW)
#define BGEMM_SMEM (2*BSTAGE*4)

template <bool HAS_BIAS>
__global__ __launch_bounds__(256) void gemmb(const __nv_bfloat16* __restrict__ Ah,
                                             const __nv_bfloat16* __restrict__ Al,
                                             const __nv_bfloat16* __restrict__ Bth,
                                             const __nv_bfloat16* __restrict__ Btl,
                                             const float* __restrict__ bias,
                                             float* __restrict__ C,
                                             int M, int N, int K) {
    extern __shared__ unsigned smu[];
    int tid  = threadIdx.x;
    int lane = tid & 31;
    int wid  = tid >> 5;
    int gid  = lane >> 2, tig = lane & 3;
    int warp_m = wid >> 2;
    int warp_n = wid & 3;

    int srow = tid >> 1;
    int soff = (tid & 1) * 8;
    size_t agoff = (size_t)(blockIdx.y * 128 + srow) * K + (tid & 1) * 16;
    size_t bgoff = (size_t)(blockIdx.x * 128 + srow) * K + (tid & 1) * 16;
    unsigned smbase = sptr(smu);

    float acc[4][4][4];
#pragma unroll
    for (int mt = 0; mt < 4; mt++)
#pragma unroll
        for (int nt = 0; nt < 4; nt++)
#pragma unroll
            for (int i = 0; i < 4; i++) acc[mt][nt][i] = 0.f;

    const int NT = K / 32;

#define GISSUE(kt, stage) do {                                               \
        unsigned d0 = smbase + ((stage) * BSTAGE + srow * BSTRW + soff) * 4; \
        const __nv_bfloat16* pah = Ah  + agoff + (size_t)(kt) * 32;          \
        const __nv_bfloat16* pal = Al  + agoff + (size_t)(kt) * 32;          \
        const __nv_bfloat16* pbh = Bth + bgoff + (size_t)(kt) * 32;          \
        const __nv_bfloat16* pbl = Btl + bgoff + (size_t)(kt) * 32;         \
        CP_ASYNC16(d0,              pah); CP_ASYNC16(d0 + 16,              pah + 8); \
        CP_ASYNC16(d0 + TW*4,       pal); CP_ASYNC16(d0 + TW*4 + 16,       pal + 8); \
        CP_ASYNC16(d0 + 2*TW*4,     pbh); CP_ASYNC16(d0 + 2*TW*4 + 16,     pbh + 8); \
        CP_ASYNC16(d0 + 3*TW*4,     pbl); CP_ASYNC16(d0 + 3*TW*4 + 16,     pbl + 8); \
        CP_COMMIT();                                                         \
    } while (0)

    GISSUE(0, 0);

    for (int kt = 0; kt < NT; kt++) {
        int cur = kt & 1;
        if (kt + 1 < NT) {
            GISSUE(kt + 1, 1 - cur);
            asm volatile("cp.async.wait_group 1;\n");
        } else {
            asm volatile("cp.async.wait_group 0;\n");
        }
        __syncthreads();

        const unsigned* SAh = smu + cur * BSTAGE;
        const unsigned* SAl = SAh + TW;
        const unsigned* SBh = SAh + 2 * TW;
        const unsigned* SBl = SAh + 3 * TW;

#pragma unroll
        for (int ks = 0; ks < 2; ks++) {
            int ko = ks * 8;
            unsigned bh[4][2], bl[4][2];
#pragma unroll
            for (int nt = 0; nt < 4; nt++) {
                int nb = (warp_n * 32 + nt * 8 + gid) * BSTRW + ko + tig;
                bh[nt][0] = SBh[nb]; bh[nt][1] = SBh[nb + 4];
                bl[nt][0] = SBl[nb]; bl[nt][1] = SBl[nb + 4];
            }
#pragma unroll
            for (int mt = 0; mt < 4; mt++) {
                int ab = (warp_m * 64 + mt * 16 + gid) * BSTRW + ko + tig;
                unsigned ah[4] = { SAh[ab], SAh[ab + 8*BSTRW], SAh[ab + 4], SAh[ab + 8*BSTRW + 4] };
                unsigned al[4] = { SAl[ab], SAl[ab + 8*BSTRW], SAl[ab + 4], SAl[ab + 8*BSTRW + 4] };
#pragma unroll
                for (int nt = 0; nt < 4; nt++) {
                    MMA_BF16(acc[mt][nt], ah, bh[nt]);
                    MMA_BF16(acc[mt][nt], ah, bl[nt]);
                    MMA_BF16(acc[mt][nt], al, bh[nt]);
                }
            }
        }
        __syncthreads();
    }

#pragma unroll
    for (int mt = 0; mt < 4; mt++) {
        int row = blockIdx.y * 128 + warp_m * 64 + mt * 16 + gid;
#pragma unroll
        for (int nt = 0; nt < 4; nt++) {
            int col = blockIdx.x * 128 + warp_n * 32 + nt * 8 + tig * 2;
            float b0 = 0.f, b1 = 0.f;
            if (HAS_BIAS) { b0 = bias[col]; b1 = bias[col + 1]; }
            float2 v0 = { acc[mt][nt][0] + b0, acc[mt][nt][1] + b1 };
            float2 v1 = { acc[mt][nt][2] + b0, acc[mt][nt][3] + b1 };
            *(float2*)&C[(size_t)row * N + col]       = v0;
            *(float2*)&C[(size_t)(row + 8) * N + col] = v1;
        }
    }
#undef GISSUE
}

// ---------------- RoPE + bf16 hi/lo split of Q,K ----------------
__global__ void rope_split_kernel(const float* __restrict__ Q, const float* __restrict__ K,
                                  const int* __restrict__ pos,
                                  __nv_bfloat16* __restrict__ Qh, __nv_bfloat16* __restrict__ Ql,
                                  __nv_bfloat16* __restrict__ Kh, __nv_bfloat16* __restrict__ Kl) {
    int idx = blockIdx.x * blockDim.x + threadIdx.x;
    const int total = SEQ * (NH + NKV) * (HD / 2);
    if (idx >= total) return;
    int d = idx & 63;
    int h = (idx >> 6) & 31;
    int s = idx >> 11;
    float inv = expf((float)d * (-13.815510557964274f / 64.0f));
    float ang = (float)pos[s] * inv;
    float si, co;
    sincosf(ang, &si, &co);
    const float* p;
    __nv_bfloat16 *oh, *ol;
    size_t base;
    if (h < NH) {
        base = (size_t)s * DQ + h * HD;
        p = Q + base; oh = Qh; ol = Ql;
    } else {
        base = (size_t)s * DKV + (h - NH) * HD;
        p = K + base; oh = Kh; ol = Kl;
    }
    float x0 = p[d];
    float x1 = p[d + 64];
    float r0 = x0 * co - x1 * si;
    float r1 = x1 * co + x0 * si;
    __nv_bfloat16 h0, l0, h1, l1;
    bsplit(r0, h0, l0);
    bsplit(r1, h1, l1);
    oh[base + d]      = h0;  ol[base + d]      = l0;
    oh[base + d + 64] = h1;  ol[base + d + 64] = l1;
}

// ---------------- V: split + transpose -> Vt[dkv][seq] bf16 hi/lo ----------------
__global__ void vsplitT_kernel(const float* __restrict__ V,
                               __nv_bfloat16* __restrict__ Vth,
                               __nv_bfloat16* __restrict__ Vtl) {
    __shared__ float t[32][33];
    int d0 = blockIdx.x * 32;
    int s0 = blockIdx.y * 32;
    int tx = threadIdx.x, ty = threadIdx.y;   // 32 x 8
#pragma unroll
    for (int i = 0; i < 4; i++)
        t[ty + 8 * i][tx] = V[(size_t)(s0 + ty + 8 * i) * DKV + d0 + tx];
    __syncthreads();
#pragma unroll
    for (int i = 0; i < 4; i++) {
        float v = t[tx][ty + 8 * i];
        __nv_bfloat16 h, l;
        bsplit(v, h, l);
        size_t o = (size_t)(d0 + ty + 8 * i) * SEQ + s0 + tx;
        Vth[o] = h;
        Vtl[o] = l;
    }
}

// ---------------- bf16x2 causal GQA flash attention ----------------
// Q tile 64x128, K tile 64x128 (x2 stages), Vt tile 128x64 (x2 stages).
// 256 thr, 8 warps (2x4). All MMAs m16n8k16 bf16, 3-product split.
#define AQSTR 68   // word stride for Q/K tiles (64 data words + 4 pad)
#define AVSTR 36   // word stride for Vt and P tiles (32 data words + 4 pad)
#define SFSTR 68   // fp32 score row stride

// word offsets
#define OQH 0
#define OQL (OQH + 64*AQSTR)              // 4352
#define OKH (OQL + 64*AQSTR)              // 8704   (2 stages x 4352)
#define OKL (OKH + 2*64*AQSTR)            // 17408
#define OVH (OKL + 2*64*AQSTR)            // 26112  (2 stages x 4608)
#define OVL (OVH + 2*128*AVSTR)           // 35328
#define OS32 (OVL + 2*128*AVSTR)          // 44544  fp32 scores 64x68
#define OPH (OS32 + 64*SFSTR)             // 48896  P hi 64x36
#define OPL (OPH + 64*AVSTR)              // 51200
#define ORM (OPL + 64*AVSTR)              // 53504
#define ATTN_WORDS (ORM + 3*64)           // 53696
#define ATTN_SMEM_BYTES (ATTN_WORDS * 4)  // 214784

__global__ __launch_bounds__(256) void attn_bf(const __nv_bfloat16* __restrict__ Qh,
                                               const __nv_bfloat16* __restrict__ Ql,
                                               const __nv_bfloat16* __restrict__ Kh,
                                               const __nv_bfloat16* __restrict__ Kl,
                                               const __nv_bfloat16* __restrict__ Vth,
                                               const __nv_bfloat16* __restrict__ Vtl,
                                               __nv_bfloat16* __restrict__ Oh,
                                               __nv_bfloat16* __restrict__ Ol) {
    extern __shared__ unsigned smw[];
    float* S32  = (float*)(smw + OS32);
    float* rowM = (float*)(smw + ORM);
    float* rowL = rowM + 64;
    float* rowC = rowL + 64;

    int qb = (int)gridDim.x - 1 - (int)blockIdx.x;   // heavy blocks first
    int h  = blockIdx.y;
    int hk = h / (NH / NKV);
    int tid  = threadIdx.x;
    int lane = tid & 31;
    int wid  = tid >> 5;
    int gid  = lane >> 2, tig = lane & 3;
    int warp_m = wid >> 2;   // 0..1
    int warp_n = wid & 3;    // 0..3
    unsigned smb = sptr(smw);

    // ---- issue Q tile loads (once) ----
#pragma unroll
    for (int j = 0; j < 4; j++) {
        int c = tid + 256 * j;
        int r = c >> 4, wo = c & 15;
        size_t g = (size_t)(qb * 64 + r) * DQ + h * HD + wo * 8;
        unsigned ds = (unsigned)(r * AQSTR + wo * 4) * 4;
        CP_ASYNC16(smb + OQH * 4 + ds, Qh + g);
        CP_ASYNC16(smb + OQL * 4 + ds, Ql + g);
    }
    // ---- issue K/Vt tile loads for kb=0, stage 0 ----
#define ISSUE_KV(kb_, st_) do {                                                   \
        for (int j = 0; j < 4; j++) {                                             \
            int c = tid + 256 * j;                                                \
            int r = c >> 4, wo = c & 15;                                          \
            size_t g = (size_t)((kb_) * 64 + r) * DKV + hk * HD + wo * 8;         \
            unsigned ds = (unsigned)((st_) * 64 * AQSTR + r * AQSTR + wo * 4) * 4;\
            CP_ASYNC16(smb + OKH * 4 + ds, Kh + g);                               \
            CP_ASYNC16(smb + OKL * 4 + ds, Kl + g);                               \
        }                                                                         \
        for (int j = 0; j < 4; j++) {                                             \
            int c = tid + 256 * j;                                                \
            int r = c >> 3, wo = c & 7;                                           \
            size_t g = (size_t)(hk * HD + r) * SEQ + (kb_) * 64 + wo * 8;         \
            unsigned ds = (unsigned)((st_) * 128 * AVSTR + r * AVSTR + wo * 4) * 4;\
            CP_ASYNC16(smb + OVH * 4 + ds, Vth + g);                              \
            CP_ASYNC16(smb + OVL * 4 + ds, Vtl + g);                              \
        }                                                                         \
    } while (0)

    ISSUE_KV(0, 0);
    CP_COMMIT();

    if (tid < 64) { rowM[tid] = -1e30f; rowL[tid] = 0.f; }

    float oacc[2][4][4];
#pragma unroll
    for (int mt = 0; mt < 2; mt++)
#pragma unroll
        for (int nt = 0; nt < 4; nt++)
#pragma unroll
            for (int i = 0; i < 4; i++) oacc[mt][nt][i] = 0.f;

    const float scale = 0.08838834764831845f;
    const unsigned* QHs = smw + OQH;
    const unsigned* QLs = smw + OQL;
    unsigned* PHs = smw + OPH;
    unsigned* PLs = smw + OPL;

    for (int kb = 0; kb <= qb; kb++) {
        int cur = kb & 1;
        asm volatile("cp.async.wait_group 0;\n");
        __syncthreads();
        if (kb < qb) {
            ISSUE_KV(kb + 1, 1 - cur);
            CP_COMMIT();
        }

        const unsigned* KHs = smw + OKH + cur * 64 * AQSTR;
        const unsigned* KLs = smw + OKL + cur * 64 * AQSTR;
        const unsigned* VHs = smw + OVH + cur * 128 * AVSTR;
        const unsigned* VLs = smw + OVL + cur * 128 * AVSTR;

        // ---- S = Q @ K^T (bf16x2, m16n8k16), warp tile 32x16 ----
        float sacc[2][2][4];
#pragma unroll
        for (int mt = 0; mt < 2; mt++)
#pragma unroll
            for (int nt = 0; nt < 2; nt++)
#pragma unroll
                for (int i = 0; i < 4; i++) sacc[mt][nt][i] = 0.f;

#pragma unroll
        for (int ks = 0; ks < 8; ks++) {
            int ko = ks * 8;
            unsigned ah[2][4], al[2][4], bh[2][2], bl[2][2];
#pragma unroll
            for (int mt = 0; mt < 2; mt++) {
                int ab = (warp_m * 32 + mt * 16 + gid) * AQSTR + ko + tig;
                ah[mt][0] = QHs[ab];     ah[mt][1] = QHs[ab + 8 * AQSTR];
                ah[mt][2] = QHs[ab + 4]; ah[mt][3] = QHs[ab + 8 * AQSTR + 4];
                al[mt][0] = QLs[ab];     al[mt][1] = QLs[ab + 8 * AQSTR];
                al[mt][2] = QLs[ab + 4]; al[mt][3] = QLs[ab + 8 * AQSTR + 4];
            }
#pragma unroll
            for (int nt = 0; nt < 2; nt++) {
                int nb = (warp_n * 16 + nt * 8 + gid) * AQSTR + ko + tig;
                bh[nt][0] = KHs[nb]; bh[nt][1] = KHs[nb + 4];
                bl[nt][0] = KLs[nb]; bl[nt][1] = KLs[nb + 4];
            }
#pragma unroll
            for (int mt = 0; mt < 2; mt++)
#pragma unroll
                for (int nt = 0; nt < 2; nt++) {
                    MMA_BF16(sacc[mt][nt], ah[mt], bh[nt]);
                    MMA_BF16(sacc[mt][nt], ah[mt], bl[nt]);
                    MMA_BF16(sacc[mt][nt], al[mt], bh[nt]);
                }
        }

        bool diag = (kb == qb);
#pragma unroll
        for (int mt = 0; mt < 2; mt++) {
            int r0 = warp_m * 32 + mt * 16 + gid;
#pragma unroll
            for (int nt = 0; nt < 2; nt++) {
                int c0 = warp_n * 16 + nt * 8 + tig * 2;
                float v00 = sacc[mt][nt][0] * scale;
                float v01 = sacc[mt][nt][1] * scale;
                float v10 = sacc[mt][nt][2] * scale;
                float v11 = sacc[mt][nt][3] * scale;
                if (diag) {
                    if (c0     > r0)     v00 = -1e30f;
                    if (c0 + 1 > r0)     v01 = -1e30f;
                    if (c0     > r0 + 8) v10 = -1e30f;
                    if (c0 + 1 > r0 + 8) v11 = -1e30f;
                }
                S32[r0 * SFSTR + c0]           = v00;
                S32[r0 * SFSTR + c0 + 1]       = v01;
                S32[(r0 + 8) * SFSTR + c0]     = v10;
                S32[(r0 + 8) * SFSTR + c0 + 1] = v11;
            }
        }
        __syncthreads();

        // ---- online softmax (4 lanes/row), write P bf16 hi/lo ----
        {
            int r = tid >> 2, sub = tid & 3;
            float mOld = rowM[r];
            float mx = mOld;
#pragma unroll
            for (int jj = 0; jj < 16; jj++)
                mx = fmaxf(mx, S32[r * SFSTR + sub * 16 + jj]);
            mx = fmaxf(mx, __shfl_xor_sync(0xffffffffu, mx, 1));
            mx = fmaxf(mx, __shfl_xor_sync(0xffffffffu, mx, 2));
            float l = 0.f;
#pragma unroll
            for (int jj = 0; jj < 16; jj += 2) {
                int j = sub * 16 + jj;
                float p0 = __expf(S32[r * SFSTR + j]     - mx);
                float p1 = __expf(S32[r * SFSTR + j + 1] - mx);
                l += p0 + p1;
                __nv_bfloat16 h0, l0, h1, l1;
                bsplit(p0, h0, l0);
                bsplit(p1, h1, l1);
                __nv_bfloat162 ph; ph.x = h0; ph.y = h1;
                __nv_bfloat162 pl; pl.x = l0; pl.y = l1;
                unsigned wph, wpl;
                memcpy(&wph, &ph, 4); memcpy(&wpl, &pl, 4);
                PHs[r * AVSTR + (j >> 1)] = wph;
                PLs[r * AVSTR + (j >> 1)] = wpl;
            }
            l += __shfl_xor_sync(0xffffffffu, l, 1);
            l += __shfl_xor_sync(0xffffffffu, l, 2);
            if (sub == 0) {
                float corr = __expf(mOld - mx);
                rowL[r] = rowL[r] * corr + l;
                rowM[r] = mx;
                rowC[r] = corr;
            }
        }
        __syncthreads();

        // ---- rescale O, then O += P @ V (bf16x2), warp tile 32x32 ----
#pragma unroll
        for (int mt = 0; mt < 2; mt++) {
            float cr0 = rowC[warp_m * 32 + mt * 16 + gid];
            float cr1 = rowC[warp_m * 32 + mt * 16 + gid + 8];
#pragma unroll
            for (int nt = 0; nt < 4; nt++) {
                oacc[mt][nt][0] *= cr0; oacc[mt][nt][1] *= cr0;
                oacc[mt][nt][2] *= cr1; oacc[mt][nt][3] *= cr1;
            }
        }
#pragma unroll
        for (int ks = 0; ks < 4; ks++) {
            int ko = ks * 8;
            unsigned ah[2][4], al[2][4], bh[4][2], bl[4][2];
#pragma unroll
            for (int mt = 0; mt < 2; mt++) {
                int ab = (warp_m * 32 + mt * 16 + gid) * AVSTR + ko + tig;
                ah[mt][0] = PHs[ab];     ah[mt][1] = PHs[ab + 8 * AVSTR];
                ah[mt][2] = PHs[ab + 4]; ah[mt][3] = PHs[ab + 8 * AVSTR + 4];
                al[mt][0] = PLs[ab];     al[mt][1] = PLs[ab + 8 * AVSTR];
                al[mt][2] = PLs[ab + 4]; al[mt][3] = PLs[ab + 8 * AVSTR + 4];
            }
#pragma unroll
            for (int nt = 0; nt < 4; nt++) {
                int nb = (warp_n * 32 + nt * 8 + gid) * AVSTR + ko + tig;
                bh[nt][0] = VHs[nb]; bh[nt][1] = VHs[nb + 4];
                bl[nt][0] = VLs[nb]; bl[nt][1] = VLs[nb + 4];
            }
#pragma unroll
            for (int mt = 0; mt < 2; mt++)
#pragma unroll
                for (int nt = 0; nt < 4; nt++) {
                    MMA_BF16(oacc[mt][nt], ah[mt], bh[nt]);
                    MMA_BF16(oacc[mt][nt], ah[mt], bl[nt]);
                    MMA_BF16(oacc[mt][nt], al[mt], bh[nt]);
                }
        }
    }
#undef ISSUE_KV

    // finalize: divide by l, write bf16 hi/lo split (feeds O-projection)
#pragma unroll
    for (int mt = 0; mt < 2; mt++) {
        int r0 = warp_m * 32 + mt * 16 + gid;
        float inv0 = 1.0f / rowL[r0];
        float inv1 = 1.0f / rowL[r0 + 8];
        int gr = qb * 64 + r0;
#pragma unroll
        for (int nt = 0; nt < 4; nt++) {
            int c = h * HD + warp_n * 32 + nt * 8 + tig * 2;
            float o00 = oacc[mt][nt][0] * inv0, o01 = oacc[mt][nt][1] * inv0;
            float o10 = oacc[mt][nt][2] * inv1, o11 = oacc[mt][nt][3] * inv1;
            __nv_bfloat16 h00, h01, h10, h11, l00, l01, l10, l11;
            bsplit(o00, h00, l00); bsplit(o01, h01, l01);
            bsplit(o10, h10, l10); bsplit(o11, h11, l11);
            __nv_bfloat162 ph0, ph1, pl0, pl1;
            ph0.x = h00; ph0.y = h01;  ph1.x = h10; ph1.y = h11;
            pl0.x = l00; pl0.y = l01;  pl1.x = l10; pl1.y = l11;
            *(__nv_bfloat162*)&Oh[(size_t)gr * DQ + c]       = ph0;
            *(__nv_bfloat162*)&Oh[(size_t)(gr + 8) * DQ + c] = ph1;
            *(__nv_bfloat162*)&Ol[(size_t)gr * DQ + c]       = pl0;
            *(__nv_bfloat162*)&Ol[(size_t)(gr + 8) * DQ + c] = pl1;
        }
    }
}

// ---------------- launch ----------------
extern "C" void kernel_launch(void* const* d_in, const int* in_sizes, int n_in,
                              void* d_out, int out_size) {
    const float* x    = (const float*)d_in[0];
    const int*   pos  = (const int*)d_in[1];
    const int*   qw_q = (const int*)d_in[2];
    const int*   qz_q = (const int*)d_in[3];
    const float* sc_q = (const float*)d_in[4];
    const float* b_q  = (const float*)d_in[5];
    const int*   qw_k = (const int*)d_in[6];
    const int*   qz_k = (const int*)d_in[7];
    const float* sc_k = (const float*)d_in[8];
    const float* b_k  = (const float*)d_in[9];
    const int*   qw_v = (const int*)d_in[10];
    const int*   qz_v = (const int*)d_in[11];
    const float* sc_v = (const float*)d_in[12];
    const float* b_v  = (const float*)d_in[13];
    const int*   qw_o = (const int*)d_in[14];
    const int*   qz_o = (const int*)d_in[15];
    const float* sc_o = (const float*)d_in[16];
    float* out = (float*)d_out;

    __nv_bfloat16 *WqTh,*WqTl,*WkTh,*WkTl,*WvTh,*WvTl,*WoTh,*WoTl,*Xh,*Xl,*Obh,*Obl;
    __nv_bfloat16 *Qbh,*Qbl,*Kbh,*Kbl,*Vth,*Vtl;
    float *Qb,*Kb,*Vb;
    cudaGetSymbolAddress((void**)&WqTh, g_WqT_h); cudaGetSymbolAddress((void**)&WqTl, g_WqT_l);
    cudaGetSymbolAddress((void**)&WkTh, g_WkT_h); cudaGetSymbolAddress((void**)&WkTl, g_WkT_l);
    cudaGetSymbolAddress((void**)&WvTh, g_WvT_h); cudaGetSymbolAddress((void**)&WvTl, g_WvT_l);
    cudaGetSymbolAddress((void**)&WoTh, g_WoT_h); cudaGetSymbolAddress((void**)&WoTl, g_WoT_l);
    cudaGetSymbolAddress((void**)&Xh, g_Xh);      cudaGetSymbolAddress((void**)&Xl, g_Xl);
    cudaGetSymbolAddress((void**)&Obh, g_Obh);    cudaGetSymbolAddress((void**)&Obl, g_Obl);
    cudaGetSymbolAddress((void**)&Qbh, g_Qbh);    cudaGetSymbolAddress((void**)&Qbl, g_Qbl);
    cudaGetSymbolAddress((void**)&Kbh, g_Kbh);    cudaGetSymbolAddress((void**)&Kbl, g_Kbl);
    cudaGetSymbolAddress((void**)&Vth, g_Vth);    cudaGetSymbolAddress((void**)&Vtl, g_Vtl);
    cudaGetSymbolAddress((void**)&Qb, g_Q);
    cudaGetSymbolAddress((void**)&Kb, g_K);
    cudaGetSymbolAddress((void**)&Vb, g_V);

    cudaFuncSetAttribute(gemmb<true>,  cudaFuncAttributeMaxDynamicSharedMemorySize, BGEMM_SMEM);
    cudaFuncSetAttribute(gemmb<false>, cudaFuncAttributeMaxDynamicSharedMemorySize, BGEMM_SMEM);
    cudaFuncSetAttribute(attn_bf, cudaFuncAttributeMaxDynamicSharedMemorySize, ATTN_SMEM_BYTES);

    // dequant -> transposed bf16 hi/lo weights
    {
        int t_q = DQ  * (HID / 8);
        int t_kv = DKV * (HID / 8);
        int t_o = HID * (DQ / 8);
        dequantT_kernel<<<(t_q  + 255) / 256, 256>>>(qw_q, qz_q, sc_q, WqTh, WqTl, HID, DQ);
        dequantT_kernel<<<(t_kv + 255) / 256, 256>>>(qw_k, qz_k, sc_k, WkTh, WkTl, HID, DKV);
        dequantT_kernel<<<(t_kv + 255) / 256, 256>>>(qw_v, qz_v, sc_v, WvTh, WvTl, HID, DKV);
        dequantT_kernel<<<(t_o  + 255) / 256, 256>>>(qw_o, qz_o, sc_o, WoTh, WoTl, DQ, HID);
    }

    // split activations to bf16 hi/lo
    {
        int n = SEQ * HID;
        splitb_kernel<<<(n + 255) / 256, 256>>>(x, Xh, Xl, n);
    }

    // projections (+bias), bf16x2-split MMAs -> fp32 Q/K/V
    gemmb<true><<<dim3(DQ / 128, SEQ / 128), 256, BGEMM_SMEM>>>(Xh, Xl, WqTh, WqTl, b_q, Qb, SEQ, DQ, HID);
    gemmb<true><<<dim3(DKV / 128, SEQ / 128), 256, BGEMM_SMEM>>>(Xh, Xl, WkTh, WkTl, b_k, Kb, SEQ, DKV, HID);
    gemmb<true><<<dim3(DKV / 128, SEQ / 128), 256, BGEMM_SMEM>>>(Xh, Xl, WvTh, WvTl, b_v, Vb, SEQ, DKV, HID);

    // RoPE + split Q,K to bf16 hi/lo
    {
        int total = SEQ * (NH + NKV) * (HD / 2);
        rope_split_kernel<<<(total + 255) / 256, 256>>>(Qb, Kb, pos, Qbh, Qbl, Kbh, Kbl);
    }
    // V split + transpose
    vsplitT_kernel<<<dim3(DKV / 32, SEQ / 32), dim3(32, 8)>>>(Vb, Vth, Vtl);

    // attention (bf16x2), outputs bf16 hi/lo split
    attn_bf<<<dim3(SEQ / 64, NH), 256, ATTN_SMEM_BYTES>>>(Qbh, Qbl, Kbh, Kbl, Vth, Vtl, Obh, Obl);

    // output projection straight into d_out
    gemmb<false><<<dim3(HID / 128, SEQ / 128), 256, BGEMM_SMEM>>>(Obh, Obl, WoTh, WoTl, nullptr, out, SEQ, HID, DQ);
}

// round 9
// speedup vs baseline: 3.8163x; 1.1699x over previous
#include <cuda_runtime.h>
#include <cuda_bf16.h>
#include <cstdint>
#include <cstddef>
#include <cstring>

// ---------------- problem constants ----------------
#define HID   3584
#define NH    28
#define NKV   4
#define HD    128
#define SEQ   2048
#define DQ    (NH*HD)     // 3584
#define DKV   (NKV*HD)    // 512
#define GRP   128

// ---------------- device scratch ----------------
// transposed INTEGER-valued bf16 weights: Wt[n][k] = (w - z), exact
__device__ __nv_bfloat16 g_WqT[(size_t)DQ * HID];
__device__ __nv_bfloat16 g_WkT[(size_t)DKV * HID];
__device__ __nv_bfloat16 g_WvT[(size_t)DKV * HID];
__device__ __nv_bfloat16 g_WoT[(size_t)HID * DQ];
// activations bf16 hi/lo
__device__ __nv_bfloat16 g_Xh[SEQ * HID], g_Xl[SEQ * HID];
// fp32 projection outputs
__device__ float g_Q[SEQ * DQ];
__device__ float g_K[SEQ * DKV];
__device__ float g_V[SEQ * DKV];
// attention inputs, bf16 hi/lo (Q/K after rope; V transposed per head: [DKV][SEQ])
__device__ __nv_bfloat16 g_Qbh[SEQ * DQ],  g_Qbl[SEQ * DQ];
__device__ __nv_bfloat16 g_Kbh[SEQ * DKV], g_Kbl[SEQ * DKV];
__device__ __nv_bfloat16 g_Vth[(size_t)DKV * SEQ], g_Vtl[(size_t)DKV * SEQ];
// attention output bf16 hi/lo
__device__ __nv_bfloat16 g_Obh[SEQ * DQ], g_Obl[SEQ * DQ];

// ---------------- helpers ----------------
__device__ __forceinline__ unsigned sptr(const void* p) {
    return (unsigned)__cvta_generic_to_shared(p);
}

#define CP_ASYNC16(dst, src) \
    asm volatile("cp.async.cg.shared.global [%0], [%1], 16;\n" :: "r"(dst), "l"(src))
#define CP_COMMIT() asm volatile("cp.async.commit_group;\n")

#define MMA_BF16(C, Aa, Bb) \
    asm volatile("mma.sync.aligned.m16n8k16.row.col.f32.bf16.bf16.f32 " \
        "{%0,%1,%2,%3},{%4,%5,%6,%7},{%8,%9},{%0,%1,%2,%3};" \
        : "+f"(C[0]), "+f"(C[1]), "+f"(C[2]), "+f"(C[3]) \
        : "r"(Aa[0]), "r"(Aa[1]), "r"(Aa[2]), "r"(Aa[3]), "r"(Bb[0]), "r"(Bb[1]))

__device__ __forceinline__ void bsplit(float v, __nv_bfloat16& h, __nv_bfloat16& l) {
    h = __float2bfloat16_rn(v);
    l = __float2bfloat16_rn(v - __bfloat162float(h));
}

// ---------------- AWQ dequant -> transposed INT bf16 Wt[n][k] (exact) ----------------
__global__ void dequantTI_kernel(const int* __restrict__ qw, const int* __restrict__ qz,
                                 __nv_bfloat16* __restrict__ W,
                                 int din, int dout) {
    int idx = blockIdx.x * blockDim.x + threadIdx.x;
    int total = dout * (din >> 3);
    if (idx >= total) return;
    int n    = idx % dout;
    int kblk = idx / dout;
    int dout8 = dout >> 3;
    int pcol = n >> 3;
    int shift = (n & 7) * 4;
    int grp = (kblk * 8) >> 7;
    int z = (qz[(size_t)grp * dout8 + pcol] >> shift) & 0xF;
    __nv_bfloat16 hv[8];
#pragma unroll
    for (int j = 0; j < 8; j++) {
        int k = kblk * 8 + j;
        int w = (qw[(size_t)k * dout8 + pcol] >> shift) & 0xF;
        hv[j] = __float2bfloat16_rn((float)(w - z));   // exact: |w-z| <= 15
    }
    size_t off = (size_t)n * din + kblk * 8;
    *(float4*)&W[off] = *(float4*)hv;
}

// ---------------- split fp32 -> bf16 hi/lo ----------------
__global__ void splitb_kernel(const float* __restrict__ in,
                              __nv_bfloat16* __restrict__ hi,
                              __nv_bfloat16* __restrict__ lo, int n) {
    int i = blockIdx.x * blockDim.x + threadIdx.x;
    if (i < n) {
        __nv_bfloat16 h, l;
        bsplit(in[i], h, l);
        hi[i] = h;
        lo[i] = l;
    }
}

// ---------------- group-scaled bf16 tensor-core GEMM ----------------
// C[M,N] = sum_g s[g][n] * (A[M,Kg] @ BtInt[N,Kg]^T) + bias
// A given as bf16 hi/lo; BtInt integer-valued bf16 (exact). Group = 128 k = 4 k-tiles.
// 128x128x32 tile, 256 thr (8 warps 2x4), warp tile 64x32, mma m16n8k16,
// 2 MMAs per k16 (xh*w + xl*w). 2-stage cp.async.
#define BSTRW 20                 // smem row stride in 32-bit words (40 bf16)
#define TW (128*BSTRW)           // words per array per stage = 2560
#define SSTAGE (3*TW)            // Ah|Al|B per stage = 7680 words
#define SGEMM_SMEM (2*SSTAGE*4)  // 61440 bytes

template <bool HAS_BIAS>
__global__ __launch_bounds__(256) void gemms(const __nv_bfloat16* __restrict__ Ah,
                                             const __nv_bfloat16* __restrict__ Al,
                                             const __nv_bfloat16* __restrict__ Bt,
                                             const float* __restrict__ sc,
                                             const float* __restrict__ bias,
                                             float* __restrict__ C,
                                             int M, int N, int K) {
    extern __shared__ unsigned smu[];
    int tid  = threadIdx.x;
    int lane = tid & 31;
    int wid  = tid >> 5;
    int gid  = lane >> 2, tig = lane & 3;
    int warp_m = wid >> 2;
    int warp_n = wid & 3;

    int srow = tid >> 1;
    int soff = (tid & 1) * 8;
    size_t agoff = (size_t)(blockIdx.y * 128 + srow) * K + (tid & 1) * 16;
    size_t bgoff = (size_t)(blockIdx.x * 128 + srow) * K + (tid & 1) * 16;
    unsigned smbase = sptr(smu);

    float acc[4][4][4];    // scaled totals
    float part[4][4][4];   // per-group partials
#pragma unroll
    for (int mt = 0; mt < 4; mt++)
#pragma unroll
        for (int nt = 0; nt < 4; nt++)
#pragma unroll
            for (int i = 0; i < 4; i++) { acc[mt][nt][i] = 0.f; part[mt][nt][i] = 0.f; }

    const int NT = K / 32;

#define GISSUE(kt, stage) do {                                               \
        unsigned d0 = smbase + ((stage) * SSTAGE + srow * BSTRW + soff) * 4; \
        const __nv_bfloat16* pah = Ah + agoff + (size_t)(kt) * 32;           \
        const __nv_bfloat16* pal = Al + agoff + (size_t)(kt) * 32;           \
        const __nv_bfloat16* pb  = Bt + bgoff + (size_t)(kt) * 32;           \
        CP_ASYNC16(d0,          pah); CP_ASYNC16(d0 + 16,          pah + 8); \
        CP_ASYNC16(d0 + TW*4,   pal); CP_ASYNC16(d0 + TW*4 + 16,   pal + 8); \
        CP_ASYNC16(d0 + 2*TW*4, pb);  CP_ASYNC16(d0 + 2*TW*4 + 16, pb + 8);  \
        CP_COMMIT();                                                         \
    } while (0)

    GISSUE(0, 0);

    for (int kt = 0; kt < NT; kt++) {
        int cur = kt & 1;
        if (kt + 1 < NT) {
            GISSUE(kt + 1, 1 - cur);
            asm volatile("cp.async.wait_group 1;\n");
        } else {
            asm volatile("cp.async.wait_group 0;\n");
        }
        __syncthreads();

        const unsigned* SAh = smu + cur * SSTAGE;
        const unsigned* SAl = SAh + TW;
        const unsigned* SB  = SAh + 2 * TW;

#pragma unroll
        for (int ks = 0; ks < 2; ks++) {
            int ko = ks * 8;
            unsigned b[4][2];
#pragma unroll
            for (int nt = 0; nt < 4; nt++) {
                int nb = (warp_n * 32 + nt * 8 + gid) * BSTRW + ko + tig;
                b[nt][0] = SB[nb]; b[nt][1] = SB[nb + 4];
            }
#pragma unroll
            for (int mt = 0; mt < 4; mt++) {
                int ab = (warp_m * 64 + mt * 16 + gid) * BSTRW + ko + tig;
                unsigned ah[4] = { SAh[ab], SAh[ab + 8*BSTRW], SAh[ab + 4], SAh[ab + 8*BSTRW + 4] };
                unsigned al[4] = { SAl[ab], SAl[ab + 8*BSTRW], SAl[ab + 4], SAl[ab + 8*BSTRW + 4] };
#pragma unroll
                for (int nt = 0; nt < 4; nt++) {
                    MMA_BF16(part[mt][nt], ah, b[nt]);
                    MMA_BF16(part[mt][nt], al, b[nt]);
                }
            }
        }
        __syncthreads();

        // fold group partials with per-(group, column) scale every 4 k-tiles (= GRP k)
        if ((kt & 3) == 3) {
            int g = kt >> 2;
#pragma unroll
            for (int nt = 0; nt < 4; nt++) {
                int col = blockIdx.x * 128 + warp_n * 32 + nt * 8 + tig * 2;
                float2 s2 = *(const float2*)&sc[(size_t)g * N + col];
#pragma unroll
                for (int mt = 0; mt < 4; mt++) {
                    acc[mt][nt][0] += part[mt][nt][0] * s2.x;
                    acc[mt][nt][1] += part[mt][nt][1] * s2.y;
                    acc[mt][nt][2] += part[mt][nt][2] * s2.x;
                    acc[mt][nt][3] += part[mt][nt][3] * s2.y;
                    part[mt][nt][0] = 0.f; part[mt][nt][1] = 0.f;
                    part[mt][nt][2] = 0.f; part[mt][nt][3] = 0.f;
                }
            }
        }
    }

#pragma unroll
    for (int mt = 0; mt < 4; mt++) {
        int row = blockIdx.y * 128 + warp_m * 64 + mt * 16 + gid;
#pragma unroll
        for (int nt = 0; nt < 4; nt++) {
            int col = blockIdx.x * 128 + warp_n * 32 + nt * 8 + tig * 2;
            float b0 = 0.f, b1 = 0.f;
            if (HAS_BIAS) { b0 = bias[col]; b1 = bias[col + 1]; }
            float2 v0 = { acc[mt][nt][0] + b0, acc[mt][nt][1] + b1 };
            float2 v1 = { acc[mt][nt][2] + b0, acc[mt][nt][3] + b1 };
            *(float2*)&C[(size_t)row * N + col]       = v0;
            *(float2*)&C[(size_t)(row + 8) * N + col] = v1;
        }
    }
#undef GISSUE
}

// ---------------- RoPE + bf16 hi/lo split of Q,K ----------------
__global__ void rope_split_kernel(const float* __restrict__ Q, const float* __restrict__ K,
                                  const int* __restrict__ pos,
                                  __nv_bfloat16* __restrict__ Qh, __nv_bfloat16* __restrict__ Ql,
                                  __nv_bfloat16* __restrict__ Kh, __nv_bfloat16* __restrict__ Kl) {
    int idx = blockIdx.x * blockDim.x + threadIdx.x;
    const int total = SEQ * (NH + NKV) * (HD / 2);
    if (idx >= total) return;
    int d = idx & 63;
    int h = (idx >> 6) & 31;
    int s = idx >> 11;
    float inv = expf((float)d * (-13.815510557964274f / 64.0f));
    float ang = (float)pos[s] * inv;
    float si, co;
    sincosf(ang, &si, &co);
    const float* p;
    __nv_bfloat16 *oh, *ol;
    size_t base;
    if (h < NH) {
        base = (size_t)s * DQ + h * HD;
        p = Q + base; oh = Qh; ol = Ql;
    } else {
        base = (size_t)s * DKV + (h - NH) * HD;
        p = K + base; oh = Kh; ol = Kl;
    }
    float x0 = p[d];
    float x1 = p[d + 64];
    float r0 = x0 * co - x1 * si;
    float r1 = x1 * co + x0 * si;
    __nv_bfloat16 h0, l0, h1, l1;
    bsplit(r0, h0, l0);
    bsplit(r1, h1, l1);
    oh[base + d]      = h0;  ol[base + d]      = l0;
    oh[base + d + 64] = h1;  ol[base + d + 64] = l1;
}

// ---------------- V: split + transpose -> Vt[dkv][seq] bf16 hi/lo ----------------
__global__ void vsplitT_kernel(const float* __restrict__ V,
                               __nv_bfloat16* __restrict__ Vth,
                               __nv_bfloat16* __restrict__ Vtl) {
    __shared__ float t[32][33];
    int d0 = blockIdx.x * 32;
    int s0 = blockIdx.y * 32;
    int tx = threadIdx.x, ty = threadIdx.y;   // 32 x 8
#pragma unroll
    for (int i = 0; i < 4; i++)
        t[ty + 8 * i][tx] = V[(size_t)(s0 + ty + 8 * i) * DKV + d0 + tx];
    __syncthreads();
#pragma unroll
    for (int i = 0; i < 4; i++) {
        float v = t[tx][ty + 8 * i];
        __nv_bfloat16 h, l;
        bsplit(v, h, l);
        size_t o = (size_t)(d0 + ty + 8 * i) * SEQ + s0 + tx;
        Vth[o] = h;
        Vtl[o] = l;
    }
}

// ---------------- bf16x2 causal GQA flash attention ----------------
#define AQSTR 68
#define AVSTR 36
#define SFSTR 68

#define OQH 0
#define OQL (OQH + 64*AQSTR)
#define OKH (OQL + 64*AQSTR)
#define OKL (OKH + 2*64*AQSTR)
#define OVH (OKL + 2*64*AQSTR)
#define OVL (OVH + 2*128*AVSTR)
#define OS32 (OVL + 2*128*AVSTR)
#define OPH (OS32 + 64*SFSTR)
#define OPL (OPH + 64*AVSTR)
#define ORM (OPL + 64*AVSTR)
#define ATTN_WORDS (ORM + 3*64)
#define ATTN_SMEM_BYTES (ATTN_WORDS * 4)

__global__ __launch_bounds__(256) void attn_bf(const __nv_bfloat16* __restrict__ Qh,
                                               const __nv_bfloat16* __restrict__ Ql,
                                               const __nv_bfloat16* __restrict__ Kh,
                                               const __nv_bfloat16* __restrict__ Kl,
                                               const __nv_bfloat16* __restrict__ Vth,
                                               const __nv_bfloat16* __restrict__ Vtl,
                                               __nv_bfloat16* __restrict__ Oh,
                                               __nv_bfloat16* __restrict__ Ol) {
    extern __shared__ unsigned smw[];
    float* S32  = (float*)(smw + OS32);
    float* rowM = (float*)(smw + ORM);
    float* rowL = rowM + 64;
    float* rowC = rowL + 64;

    int qb = (int)gridDim.x - 1 - (int)blockIdx.x;
    int h  = blockIdx.y;
    int hk = h / (NH / NKV);
    int tid  = threadIdx.x;
    int lane = tid & 31;
    int wid  = tid >> 5;
    int gid  = lane >> 2, tig = lane & 3;
    int warp_m = wid >> 2;
    int warp_n = wid & 3;
    unsigned smb = sptr(smw);

#pragma unroll
    for (int j = 0; j < 4; j++) {
        int c = tid + 256 * j;
        int r = c >> 4, wo = c & 15;
        size_t g = (size_t)(qb * 64 + r) * DQ + h * HD + wo * 8;
        unsigned ds = (unsigned)(r * AQSTR + wo * 4) * 4;
        CP_ASYNC16(smb + OQH * 4 + ds, Qh + g);
        CP_ASYNC16(smb + OQL * 4 + ds, Ql + g);
    }
#define ISSUE_KV(kb_, st_) do {                                                   \
        for (int j = 0; j < 4; j++) {                                             \
            int c = tid + 256 * j;                                                \
            int r = c >> 4, wo = c & 15;                                          \
            size_t g = (size_t)((kb_) * 64 + r) * DKV + hk * HD + wo * 8;         \
            unsigned ds = (unsigned)((st_) * 64 * AQSTR + r * AQSTR + wo * 4) * 4;\
            CP_ASYNC16(smb + OKH * 4 + ds, Kh + g);                               \
            CP_ASYNC16(smb + OKL * 4 + ds, Kl + g);                               \
        }                                                                         \
        for (int j = 0; j < 4; j++) {                                             \
            int c = tid + 256 * j;                                                \
            int r = c >> 3, wo = c & 7;                                           \
            size_t g = (size_t)(hk * HD + r) * SEQ + (kb_) * 64 + wo * 8;         \
            unsigned ds = (unsigned)((st_) * 128 * AVSTR + r * AVSTR + wo * 4) * 4;\
            CP_ASYNC16(smb + OVH * 4 + ds, Vth + g);                              \
            CP_ASYNC16(smb + OVL * 4 + ds, Vtl + g);                              \
        }                                                                         \
    } while (0)

    ISSUE_KV(0, 0);
    CP_COMMIT();

    if (tid < 64) { rowM[tid] = -1e30f; rowL[tid] = 0.f; }

    float oacc[2][4][4];
#pragma unroll
    for (int mt = 0; mt < 2; mt++)
#pragma unroll
        for (int nt = 0; nt < 4; nt++)
#pragma unroll
            for (int i = 0; i < 4; i++) oacc[mt][nt][i] = 0.f;

    const float scale = 0.08838834764831845f;
    const unsigned* QHs = smw + OQH;
    const unsigned* QLs = smw + OQL;
    unsigned* PHs = smw + OPH;
    unsigned* PLs = smw + OPL;

    for (int kb = 0; kb <= qb; kb++) {
        int cur = kb & 1;
        asm volatile("cp.async.wait_group 0;\n");
        __syncthreads();
        if (kb < qb) {
            ISSUE_KV(kb + 1, 1 - cur);
            CP_COMMIT();
        }

        const unsigned* KHs = smw + OKH + cur * 64 * AQSTR;
        const unsigned* KLs = smw + OKL + cur * 64 * AQSTR;
        const unsigned* VHs = smw + OVH + cur * 128 * AVSTR;
        const unsigned* VLs = smw + OVL + cur * 128 * AVSTR;

        float sacc[2][2][4];
#pragma unroll
        for (int mt = 0; mt < 2; mt++)
#pragma unroll
            for (int nt = 0; nt < 2; nt++)
#pragma unroll
                for (int i = 0; i < 4; i++) sacc[mt][nt][i] = 0.f;

#pragma unroll
        for (int ks = 0; ks < 8; ks++) {
            int ko = ks * 8;
            unsigned ah[2][4], al[2][4], bh[2][2], bl[2][2];
#pragma unroll
            for (int mt = 0; mt < 2; mt++) {
                int ab = (warp_m * 32 + mt * 16 + gid) * AQSTR + ko + tig;
                ah[mt][0] = QHs[ab];     ah[mt][1] = QHs[ab + 8 * AQSTR];
                ah[mt][2] = QHs[ab + 4]; ah[mt][3] = QHs[ab + 8 * AQSTR + 4];
                al[mt][0] = QLs[ab];     al[mt][1] = QLs[ab + 8 * AQSTR];
                al[mt][2] = QLs[ab + 4]; al[mt][3] = QLs[ab + 8 * AQSTR + 4];
            }
#pragma unroll
            for (int nt = 0; nt < 2; nt++) {
                int nb = (warp_n * 16 + nt * 8 + gid) * AQSTR + ko + tig;
                bh[nt][0] = KHs[nb]; bh[nt][1] = KHs[nb + 4];
                bl[nt][0] = KLs[nb]; bl[nt][1] = KLs[nb + 4];
            }
#pragma unroll
            for (int mt = 0; mt < 2; mt++)
#pragma unroll
                for (int nt = 0; nt < 2; nt++) {
                    MMA_BF16(sacc[mt][nt], ah[mt], bh[nt]);
                    MMA_BF16(sacc[mt][nt], ah[mt], bl[nt]);
                    MMA_BF16(sacc[mt][nt], al[mt], bh[nt]);
                }
        }

        bool diag = (kb == qb);
#pragma unroll
        for (int mt = 0; mt < 2; mt++) {
            int r0 = warp_m * 32 + mt * 16 + gid;
#pragma unroll
            for (int nt = 0; nt < 2; nt++) {
                int c0 = warp_n * 16 + nt * 8 + tig * 2;
                float v00 = sacc[mt][nt][0] * scale;
                float v01 = sacc[mt][nt][1] * scale;
                float v10 = sacc[mt][nt][2] * scale;
                float v11 = sacc[mt][nt][3] * scale;
                if (diag) {
                    if (c0     > r0)     v00 = -1e30f;
                    if (c0 + 1 > r0)     v01 = -1e30f;
                    if (c0     > r0 + 8) v10 = -1e30f;
                    if (c0 + 1 > r0 + 8) v11 = -1e30f;
                }
                S32[r0 * SFSTR + c0]           = v00;
                S32[r0 * SFSTR + c0 + 1]       = v01;
                S32[(r0 + 8) * SFSTR + c0]     = v10;
                S32[(r0 + 8) * SFSTR + c0 + 1] = v11;
            }
        }
        __syncthreads();

        {
            int r = tid >> 2, sub = tid & 3;
            float mOld = rowM[r];
            float mx = mOld;
#pragma unroll
            for (int jj = 0; jj < 16; jj++)
                mx = fmaxf(mx, S32[r * SFSTR + sub * 16 + jj]);
            mx = fmaxf(mx, __shfl_xor_sync(0xffffffffu, mx, 1));
            mx = fmaxf(mx, __shfl_xor_sync(0xffffffffu, mx, 2));
            float l = 0.f;
#pragma unroll
            for (int jj = 0; jj < 16; jj += 2) {
                int j = sub * 16 + jj;
                float p0 = __expf(S32[r * SFSTR + j]     - mx);
                float p1 = __expf(S32[r * SFSTR + j + 1] - mx);
                l += p0 + p1;
                __nv_bfloat16 h0, l0, h1, l1;
                bsplit(p0, h0, l0);
                bsplit(p1, h1, l1);
                __nv_bfloat162 ph; ph.x = h0; ph.y = h1;
                __nv_bfloat162 pl; pl.x = l0; pl.y = l1;
                unsigned wph, wpl;
                memcpy(&wph, &ph, 4); memcpy(&wpl, &pl, 4);
                PHs[r * AVSTR + (j >> 1)] = wph;
                PLs[r * AVSTR + (j >> 1)] = wpl;
            }
            l += __shfl_xor_sync(0xffffffffu, l, 1);
            l += __shfl_xor_sync(0xffffffffu, l, 2);
            if (sub == 0) {
                float corr = __expf(mOld - mx);
                rowL[r] = rowL[r] * corr + l;
                rowM[r] = mx;
                rowC[r] = corr;
            }
        }
        __syncthreads();

#pragma unroll
        for (int mt = 0; mt < 2; mt++) {
            float cr0 = rowC[warp_m * 32 + mt * 16 + gid];
            float cr1 = rowC[warp_m * 32 + mt * 16 + gid + 8];
#pragma unroll
            for (int nt = 0; nt < 4; nt++) {
                oacc[mt][nt][0] *= cr0; oacc[mt][nt][1] *= cr0;
                oacc[mt][nt][2] *= cr1; oacc[mt][nt][3] *= cr1;
            }
        }
#pragma unroll
        for (int ks = 0; ks < 4; ks++) {
            int ko = ks * 8;
            unsigned ah[2][4], al[2][4], bh[4][2], bl[4][2];
#pragma unroll
            for (int mt = 0; mt < 2; mt++) {
                int ab = (warp_m * 32 + mt * 16 + gid) * AVSTR + ko + tig;
                ah[mt][0] = PHs[ab];     ah[mt][1] = PHs[ab + 8 * AVSTR];
                ah[mt][2] = PHs[ab + 4]; ah[mt][3] = PHs[ab + 8 * AVSTR + 4];
                al[mt][0] = PLs[ab];     al[mt][1] = PLs[ab + 8 * AVSTR];
                al[mt][2] = PLs[ab + 4]; al[mt][3] = PLs[ab + 8 * AVSTR + 4];
            }
#pragma unroll
            for (int nt = 0; nt < 4; nt++) {
                int nb = (warp_n * 32 + nt * 8 + gid) * AVSTR + ko + tig;
                bh[nt][0] = VHs[nb]; bh[nt][1] = VHs[nb + 4];
                bl[nt][0] = VLs[nb]; bl[nt][1] = VLs[nb + 4];
            }
#pragma unroll
            for (int mt = 0; mt < 2; mt++)
#pragma unroll
                for (int nt = 0; nt < 4; nt++) {
                    MMA_BF16(oacc[mt][nt], ah[mt], bh[nt]);
                    MMA_BF16(oacc[mt][nt], ah[mt], bl[nt]);
                    MMA_BF16(oacc[mt][nt], al[mt], bh[nt]);
                }
        }
    }
#undef ISSUE_KV

#pragma unroll
    for (int mt = 0; mt < 2; mt++) {
        int r0 = warp_m * 32 + mt * 16 + gid;
        float inv0 = 1.0f / rowL[r0];
        float inv1 = 1.0f / rowL[r0 + 8];
        int gr = qb * 64 + r0;
#pragma unroll
        for (int nt = 0; nt < 4; nt++) {
            int c = h * HD + warp_n * 32 + nt * 8 + tig * 2;
            float o00 = oacc[mt][nt][0] * inv0, o01 = oacc[mt][nt][1] * inv0;
            float o10 = oacc[mt][nt][2] * inv1, o11 = oacc[mt][nt][3] * inv1;
            __nv_bfloat16 h00, h01, h10, h11, l00, l01, l10, l11;
            bsplit(o00, h00, l00); bsplit(o01, h01, l01);
            bsplit(o10, h10, l10); bsplit(o11, h11, l11);
            __nv_bfloat162 ph0, ph1, pl0, pl1;
            ph0.x = h00; ph0.y = h01;  ph1.x = h10; ph1.y = h11;
            pl0.x = l00; pl0.y = l01;  pl1.x = l10; pl1.y = l11;
            *(__nv_bfloat162*)&Oh[(size_t)gr * DQ + c]       = ph0;
            *(__nv_bfloat162*)&Oh[(size_t)(gr + 8) * DQ + c] = ph1;
            *(__nv_bfloat162*)&Ol[(size_t)gr * DQ + c]       = pl0;
            *(__nv_bfloat162*)&Ol[(size_t)(gr + 8) * DQ + c] = pl1;
        }
    }
}

// ---------------- launch ----------------
extern "C" void kernel_launch(void* const* d_in, const int* in_sizes, int n_in,
                              void* d_out, int out_size) {
    const float* x    = (const float*)d_in[0];
    const int*   pos  = (const int*)d_in[1];
    const int*   qw_q = (const int*)d_in[2];
    const int*   qz_q = (const int*)d_in[3];
    const float* sc_q = (const float*)d_in[4];
    const float* b_q  = (const float*)d_in[5];
    const int*   qw_k = (const int*)d_in[6];
    const int*   qz_k = (const int*)d_in[7];
    const float* sc_k = (const float*)d_in[8];
    const float* b_k  = (const float*)d_in[9];
    const int*   qw_v = (const int*)d_in[10];
    const int*   qz_v = (const int*)d_in[11];
    const float* sc_v = (const float*)d_in[12];
    const float* b_v  = (const float*)d_in[13];
    const int*   qw_o = (const int*)d_in[14];
    const int*   qz_o = (const int*)d_in[15];
    const float* sc_o = (const float*)d_in[16];
    float* out = (float*)d_out;

    __nv_bfloat16 *WqT,*WkT,*WvT,*WoT,*Xh,*Xl,*Obh,*Obl;
    __nv_bfloat16 *Qbh,*Qbl,*Kbh,*Kbl,*Vth,*Vtl;
    float *Qb,*Kb,*Vb;
    cudaGetSymbolAddress((void**)&WqT, g_WqT);
    cudaGetSymbolAddress((void**)&WkT, g_WkT);
    cudaGetSymbolAddress((void**)&WvT, g_WvT);
    cudaGetSymbolAddress((void**)&WoT, g_WoT);
    cudaGetSymbolAddress((void**)&Xh, g_Xh);      cudaGetSymbolAddress((void**)&Xl, g_Xl);
    cudaGetSymbolAddress((void**)&Obh, g_Obh);    cudaGetSymbolAddress((void**)&Obl, g_Obl);
    cudaGetSymbolAddress((void**)&Qbh, g_Qbh);    cudaGetSymbolAddress((void**)&Qbl, g_Qbl);
    cudaGetSymbolAddress((void**)&Kbh, g_Kbh);    cudaGetSymbolAddress((void**)&Kbl, g_Kbl);
    cudaGetSymbolAddress((void**)&Vth, g_Vth);    cudaGetSymbolAddress((void**)&Vtl, g_Vtl);
    cudaGetSymbolAddress((void**)&Qb, g_Q);
    cudaGetSymbolAddress((void**)&Kb, g_K);
    cudaGetSymbolAddress((void**)&Vb, g_V);

    cudaFuncSetAttribute(gemms<true>,  cudaFuncAttributeMaxDynamicSharedMemorySize, SGEMM_SMEM);
    cudaFuncSetAttribute(gemms<false>, cudaFuncAttributeMaxDynamicSharedMemorySize, SGEMM_SMEM);
    cudaFuncSetAttribute(attn_bf, cudaFuncAttributeMaxDynamicSharedMemorySize, ATTN_SMEM_BYTES);

    // dequant -> transposed INT bf16 weights (exact)
    {
        int t_q = DQ  * (HID / 8);
        int t_kv = DKV * (HID / 8);
        int t_o = HID * (DQ / 8);
        dequantTI_kernel<<<(t_q  + 255) / 256, 256>>>(qw_q, qz_q, WqT, HID, DQ);
        dequantTI_kernel<<<(t_kv + 255) / 256, 256>>>(qw_k, qz_k, WkT, HID, DKV);
        dequantTI_kernel<<<(t_kv + 255) / 256, 256>>>(qw_v, qz_v, WvT, HID, DKV);
        dequantTI_kernel<<<(t_o  + 255) / 256, 256>>>(qw_o, qz_o, WoT, DQ, HID);
    }

    // split activations to bf16 hi/lo
    {
        int n = SEQ * HID;
        splitb_kernel<<<(n + 255) / 256, 256>>>(x, Xh, Xl, n);
    }

    // projections (+bias): group-scaled integer-weight GEMMs
    gemms<true><<<dim3(DQ / 128, SEQ / 128), 256, SGEMM_SMEM>>>(Xh, Xl, WqT, sc_q, b_q, Qb, SEQ, DQ, HID);
    gemms<true><<<dim3(DKV / 128, SEQ / 128), 256, SGEMM_SMEM>>>(Xh, Xl, WkT, sc_k, b_k, Kb, SEQ, DKV, HID);
    gemms<true><<<dim3(DKV / 128, SEQ / 128), 256, SGEMM_SMEM>>>(Xh, Xl, WvT, sc_v, b_v, Vb, SEQ, DKV, HID);

    // RoPE + split Q,K to bf16 hi/lo
    {
        int total = SEQ * (NH + NKV) * (HD / 2);
        rope_split_kernel<<<(total + 255) / 256, 256>>>(Qb, Kb, pos, Qbh, Qbl, Kbh, Kbl);
    }
    // V split + transpose
    vsplitT_kernel<<<dim3(DKV / 32, SEQ / 32), dim3(32, 8)>>>(Vb, Vth, Vtl);

    // attention (bf16x2), outputs bf16 hi/lo split
    attn_bf<<<dim3(SEQ / 64, NH), 256, ATTN_SMEM_BYTES>>>(Qbh, Qbl, Kbh, Kbl, Vth, Vtl, Obh, Obl);

    // output projection straight into d_out
    gemms<false><<<dim3(HID / 128, SEQ / 128), 256, SGEMM_SMEM>>>(Obh, Obl, WoT, sc_o, nullptr, out, SEQ, HID, DQ);
}

// round 12
// speedup vs baseline: 4.4484x; 1.1656x over previous
#include <cuda_runtime.h>
#include <cuda_bf16.h>
#include <cstdint>
#include <cstddef>
#include <cstring>

// ---------------- problem constants ----------------
#define HID   3584
#define NH    28
#define NKV   4
#define HD    128
#define SEQ   2048
#define DQ    (NH*HD)     // 3584
#define DKV   (NKV*HD)    // 512
#define GRP   128

// ---------------- device scratch ----------------
__device__ __nv_bfloat16 g_WqT[(size_t)DQ * HID];
__device__ __nv_bfloat16 g_WkT[(size_t)DKV * HID];
__device__ __nv_bfloat16 g_WvT[(size_t)DKV * HID];
__device__ __nv_bfloat16 g_WoT[(size_t)HID * DQ];
__device__ __nv_bfloat16 g_Xh[SEQ * HID], g_Xl[SEQ * HID];
__device__ float g_Q[SEQ * DQ];
__device__ float g_K[SEQ * DKV];
__device__ float g_V[SEQ * DKV];
__device__ __nv_bfloat16 g_Qbh[SEQ * DQ],  g_Qbl[SEQ * DQ];
__device__ __nv_bfloat16 g_Kbh[SEQ * DKV], g_Kbl[SEQ * DKV];
__device__ __nv_bfloat16 g_Vth[(size_t)DKV * SEQ], g_Vtl[(size_t)DKV * SEQ];
__device__ __nv_bfloat16 g_Obh[SEQ * DQ], g_Obl[SEQ * DQ];

// ---------------- helpers ----------------
__device__ __forceinline__ unsigned sptr(const void* p) {
    return (unsigned)__cvta_generic_to_shared(p);
}

#define CP_ASYNC16(dst, src) \
    asm volatile("cp.async.cg.shared.global [%0], [%1], 16;\n" :: "r"(dst), "l"(src))
#define CP_COMMIT() asm volatile("cp.async.commit_group;\n")

#define MMA_BF16(C, Aa, Bb) \
    asm volatile("mma.sync.aligned.m16n8k16.row.col.f32.bf16.bf16.f32 " \
        "{%0,%1,%2,%3},{%4,%5,%6,%7},{%8,%9},{%0,%1,%2,%3};" \
        : "+f"(C[0]), "+f"(C[1]), "+f"(C[2]), "+f"(C[3]) \
        : "r"(Aa[0]), "r"(Aa[1]), "r"(Aa[2]), "r"(Aa[3]), "r"(Bb[0]), "r"(Bb[1]))

__device__ __forceinline__ void bsplit(float v, __nv_bfloat16& hi, __nv_bfloat16& lo) {
    hi = __float2bfloat16_rn(v);
    lo = __float2bfloat16_rn(v - __bfloat162float(hi));
}

// pack two floats into bf16x2 hi word + bf16x2 lo (residual) word
__device__ __forceinline__ void packhl(float a, float b, unsigned& wh, unsigned& wl) {
    __nv_bfloat16 ha, la, hb, lb;
    bsplit(a, ha, la);
    bsplit(b, hb, lb);
    __nv_bfloat162 th; th.x = ha; th.y = hb;
    __nv_bfloat162 tl; tl.x = la; tl.y = lb;
    memcpy(&wh, &th, 4);
    memcpy(&wl, &tl, 4);
}

// ---------------- AWQ dequant -> transposed INT bf16 Wt[n][k] (exact) ----------------
__global__ void dequantTI_kernel(const int* __restrict__ qw, const int* __restrict__ qz,
                                 __nv_bfloat16* __restrict__ W,
                                 int din, int dout) {
    int idx = blockIdx.x * blockDim.x + threadIdx.x;
    int total = dout * (din >> 3);
    if (idx >= total) return;
    int n    = idx % dout;
    int kblk = idx / dout;
    int dout8 = dout >> 3;
    int pcol = n >> 3;
    int shift = (n & 7) * 4;
    int grp = (kblk * 8) >> 7;
    int z = (qz[(size_t)grp * dout8 + pcol] >> shift) & 0xF;
    __nv_bfloat16 hv[8];
#pragma unroll
    for (int j = 0; j < 8; j++) {
        int k = kblk * 8 + j;
        int w = (qw[(size_t)k * dout8 + pcol] >> shift) & 0xF;
        hv[j] = __float2bfloat16_rn((float)(w - z));
    }
    size_t off = (size_t)n * din + kblk * 8;
    *(float4*)&W[off] = *(float4*)hv;
}

// ---------------- split fp32 -> bf16 hi/lo ----------------
__global__ void splitb_kernel(const float* __restrict__ in,
                              __nv_bfloat16* __restrict__ hi,
                              __nv_bfloat16* __restrict__ lo, int n) {
    int i = blockIdx.x * blockDim.x + threadIdx.x;
    if (i < n) {
        __nv_bfloat16 h, l;
        bsplit(in[i], h, l);
        hi[i] = h;
        lo[i] = l;
    }
}

// ---------------- group-scaled bf16 GEMM core (R9-proven) ----------------
#define BSTRW 20
#define TW (128*BSTRW)
#define SSTAGE (3*TW)
#define SGEMM_SMEM (2*SSTAGE*4)   // 61440 B

#define GEMM_BODY(NB, NN, KK, HASB)                                              \
    extern __shared__ unsigned smu[];                                            \
    int tid  = threadIdx.x;                                                      \
    int lane = tid & 31;                                                         \
    int wid  = tid >> 5;                                                         \
    int gid  = lane >> 2, tig = lane & 3;                                        \
    int warp_m = wid >> 2;                                                       \
    int warp_n = wid & 3;                                                        \
    int srow = tid >> 1;                                                         \
    int soff = (tid & 1) * 8;                                                    \
    size_t agoff = (size_t)(blockIdx.y * 128 + srow) * (KK) + (tid & 1) * 16;    \
    size_t bgoff = (size_t)((NB) * 128 + srow) * (KK) + (tid & 1) * 16;          \
    unsigned smbase = sptr(smu);                                                 \
    float acc[4][4][4];                                                          \
    float part[4][4][4];                                                         \
    _Pragma("unroll")                                                            \
    for (int mt = 0; mt < 4; mt++)                                               \
        _Pragma("unroll")                                                        \
        for (int nt = 0; nt < 4; nt++)                                           \
            _Pragma("unroll")                                                    \
            for (int i = 0; i < 4; i++) { acc[mt][nt][i] = 0.f; part[mt][nt][i] = 0.f; } \
    const int NT = (KK) / 32;                                                    \
    GISSUE(0, 0);                                                                \
    for (int kt = 0; kt < NT; kt++) {                                            \
        int cur = kt & 1;                                                        \
        if (kt + 1 < NT) {                                                       \
            GISSUE(kt + 1, 1 - cur);                                             \
            asm volatile("cp.async.wait_group 1;\n");                            \
        } else {                                                                 \
            asm volatile("cp.async.wait_group 0;\n");                            \
        }                                                                        \
        __syncthreads();                                                         \
        const unsigned* SAh = smu + cur * SSTAGE;                                \
        const unsigned* SAl = SAh + TW;                                          \
        const unsigned* SB  = SAh + 2 * TW;                                      \
        _Pragma("unroll")                                                        \
        for (int ks = 0; ks < 2; ks++) {                                         \
            int ko = ks * 8;                                                     \
            unsigned b[4][2];                                                    \
            _Pragma("unroll")                                                    \
            for (int nt = 0; nt < 4; nt++) {                                     \
                int nb2 = (warp_n * 32 + nt * 8 + gid) * BSTRW + ko + tig;       \
                b[nt][0] = SB[nb2]; b[nt][1] = SB[nb2 + 4];                      \
            }                                                                    \
            _Pragma("unroll")                                                    \
            for (int mt = 0; mt < 4; mt++) {                                     \
                int ab = (warp_m * 64 + mt * 16 + gid) * BSTRW + ko + tig;       \
                unsigned ah[4] = { SAh[ab], SAh[ab + 8*BSTRW], SAh[ab + 4], SAh[ab + 8*BSTRW + 4] }; \
                unsigned al[4] = { SAl[ab], SAl[ab + 8*BSTRW], SAl[ab + 4], SAl[ab + 8*BSTRW + 4] }; \
                _Pragma("unroll")                                                \
                for (int nt = 0; nt < 4; nt++) {                                 \
                    MMA_BF16(part[mt][nt], ah, b[nt]);                           \
                    MMA_BF16(part[mt][nt], al, b[nt]);                           \
                }                                                                \
            }                                                                    \
        }                                                                        \
        __syncthreads();                                                         \
        if ((kt & 3) == 3) {                                                     \
            int g = kt >> 2;                                                     \
            _Pragma("unroll")                                                    \
            for (int nt = 0; nt < 4; nt++) {                                     \
                int col = (NB) * 128 + warp_n * 32 + nt * 8 + tig * 2;           \
                float2 s2 = *(const float2*)&sc[(size_t)g * (NN) + col];         \
                _Pragma("unroll")                                                \
                for (int mt = 0; mt < 4; mt++) {                                 \
                    acc[mt][nt][0] += part[mt][nt][0] * s2.x;                    \
                    acc[mt][nt][1] += part[mt][nt][1] * s2.y;                    \
                    acc[mt][nt][2] += part[mt][nt][2] * s2.x;                    \
                    acc[mt][nt][3] += part[mt][nt][3] * s2.y;                    \
                    part[mt][nt][0] = 0.f; part[mt][nt][1] = 0.f;                \
                    part[mt][nt][2] = 0.f; part[mt][nt][3] = 0.f;                \
                }                                                                \
            }                                                                    \
        }                                                                        \
    }                                                                            \
    _Pragma("unroll")                                                            \
    for (int mt = 0; mt < 4; mt++) {                                             \
        int row = blockIdx.y * 128 + warp_m * 64 + mt * 16 + gid;                \
        _Pragma("unroll")                                                        \
        for (int nt = 0; nt < 4; nt++) {                                         \
            int col = (NB) * 128 + warp_n * 32 + nt * 8 + tig * 2;               \
            float b0 = 0.f, b1 = 0.f;                                            \
            if (HASB) { b0 = bias[col]; b1 = bias[col + 1]; }                    \
            float2 v0 = { acc[mt][nt][0] + b0, acc[mt][nt][1] + b1 };            \
            float2 v1 = { acc[mt][nt][2] + b0, acc[mt][nt][3] + b1 };            \
            *(float2*)&C[(size_t)row * (NN) + col]       = v0;                   \
            *(float2*)&C[(size_t)(row + 8) * (NN) + col] = v1;                   \
        }                                                                        \
    }

#define GISSUE(kt, stage) do {                                               \
        unsigned d0 = smbase + ((stage) * SSTAGE + srow * BSTRW + soff) * 4; \
        const __nv_bfloat16* pah = Ah + agoff + (size_t)(kt) * 32;           \
        const __nv_bfloat16* pal = Al + agoff + (size_t)(kt) * 32;           \
        const __nv_bfloat16* pb  = Bt + bgoff + (size_t)(kt) * 32;           \
        CP_ASYNC16(d0,          pah); CP_ASYNC16(d0 + 16,          pah + 8); \
        CP_ASYNC16(d0 + TW*4,   pal); CP_ASYNC16(d0 + TW*4 + 16,   pal + 8); \
        CP_ASYNC16(d0 + 2*TW*4, pb);  CP_ASYNC16(d0 + 2*TW*4 + 16, pb + 8);  \
        CP_COMMIT();                                                         \
    } while (0)

// fused Q/K/V projection: blockIdx.x selects (matrix, n-tile)
__global__ __launch_bounds__(256) void gemmsQKV(const __nv_bfloat16* __restrict__ Ah,
                                                const __nv_bfloat16* __restrict__ Al,
                                                const __nv_bfloat16* __restrict__ BtQ,
                                                const __nv_bfloat16* __restrict__ BtK,
                                                const __nv_bfloat16* __restrict__ BtV,
                                                const float* __restrict__ scQ,
                                                const float* __restrict__ scK,
                                                const float* __restrict__ scV,
                                                const float* __restrict__ bQ,
                                                const float* __restrict__ bK,
                                                const float* __restrict__ bV,
                                                float* __restrict__ CQ,
                                                float* __restrict__ CK,
                                                float* __restrict__ CV) {
    int bx = blockIdx.x;
    const __nv_bfloat16* Bt;
    const float* sc;
    const float* bias;
    float* C;
    int N, nb;
    if (bx < 28)      { Bt = BtQ; sc = scQ; bias = bQ; C = CQ; N = DQ;  nb = bx; }
    else if (bx < 32) { Bt = BtK; sc = scK; bias = bK; C = CK; N = DKV; nb = bx - 28; }
    else              { Bt = BtV; sc = scV; bias = bV; C = CV; N = DKV; nb = bx - 32; }
    GEMM_BODY(nb, N, HID, true)
}

// O-projection (no bias)
__global__ __launch_bounds__(256) void gemmsO(const __nv_bfloat16* __restrict__ Ah,
                                              const __nv_bfloat16* __restrict__ Al,
                                              const __nv_bfloat16* __restrict__ Bt,
                                              const float* __restrict__ sc,
                                              const float* __restrict__ bias,
                                              float* __restrict__ C) {
    GEMM_BODY((int)blockIdx.x, HID, DQ, false)
}
#undef GISSUE

// ---------------- RoPE + bf16 hi/lo split of Q,K ----------------
__global__ void rope_split_kernel(const float* __restrict__ Q, const float* __restrict__ K,
                                  const int* __restrict__ pos,
                                  __nv_bfloat16* __restrict__ Qh, __nv_bfloat16* __restrict__ Ql,
                                  __nv_bfloat16* __restrict__ Kh, __nv_bfloat16* __restrict__ Kl) {
    int idx = blockIdx.x * blockDim.x + threadIdx.x;
    const int total = SEQ * (NH + NKV) * (HD / 2);
    if (idx >= total) return;
    int d = idx & 63;
    int h = (idx >> 6) & 31;
    int s = idx >> 11;
    float inv = expf((float)d * (-13.815510557964274f / 64.0f));
    float ang = (float)pos[s] * inv;
    float si, co;
    sincosf(ang, &si, &co);
    const float* p;
    __nv_bfloat16 *oh, *ol;
    size_t base;
    if (h < NH) {
        base = (size_t)s * DQ + h * HD;
        p = Q + base; oh = Qh; ol = Ql;
    } else {
        base = (size_t)s * DKV + (h - NH) * HD;
        p = K + base; oh = Kh; ol = Kl;
    }
    float x0 = p[d];
    float x1 = p[d + 64];
    float r0 = x0 * co - x1 * si;
    float r1 = x1 * co + x0 * si;
    __nv_bfloat16 h0, l0, h1, l1;
    bsplit(r0, h0, l0);
    bsplit(r1, h1, l1);
    oh[base + d]      = h0;  ol[base + d]      = l0;
    oh[base + d + 64] = h1;  ol[base + d + 64] = l1;
}

// ---------------- V: split + transpose -> Vt[dkv][seq] bf16 hi/lo ----------------
__global__ void vsplitT_kernel(const float* __restrict__ V,
                               __nv_bfloat16* __restrict__ Vth,
                               __nv_bfloat16* __restrict__ Vtl) {
    __shared__ float t[32][33];
    int d0 = blockIdx.x * 32;
    int s0 = blockIdx.y * 32;
    int tx = threadIdx.x, ty = threadIdx.y;
#pragma unroll
    for (int i = 0; i < 4; i++)
        t[ty + 8 * i][tx] = V[(size_t)(s0 + ty + 8 * i) * DKV + d0 + tx];
    __syncthreads();
#pragma unroll
    for (int i = 0; i < 4; i++) {
        float v = t[tx][ty + 8 * i];
        __nv_bfloat16 h, l;
        bsplit(v, h, l);
        size_t o = (size_t)(d0 + ty + 8 * i) * SEQ + s0 + tx;
        Vth[o] = h;
        Vtl[o] = l;
    }
}

// ---------------- FA2-style bf16x2 causal GQA attention ----------------
// QB=128 rows/CTA, K tile 64, 8 warps each owning 16 full rows.
// P stays in registers (accumulator fragment == A fragment after bf16x2 pack).
#define QSTR2 68
#define KSTR2 68
#define VSTR2 36
#define O2QH 0
#define O2QL (O2QH + 128*QSTR2)            // 8704
#define O2KH (O2QL + 128*QSTR2)            // 17408
#define O2KL (O2KH + 2*64*KSTR2)           // 26112
#define O2VH (O2KL + 2*64*KSTR2)           // 34816
#define O2VL (O2VH + 2*128*VSTR2)          // 44032
#define ATTN2_WORDS (O2VL + 2*128*VSTR2)   // 53248
#define ATTN2_SMEM (ATTN2_WORDS * 4)       // 212992 B

__global__ __launch_bounds__(256) void attn_bf2(const __nv_bfloat16* __restrict__ Qh,
                                                const __nv_bfloat16* __restrict__ Ql,
                                                const __nv_bfloat16* __restrict__ Kh,
                                                const __nv_bfloat16* __restrict__ Kl,
                                                const __nv_bfloat16* __restrict__ Vth,
                                                const __nv_bfloat16* __restrict__ Vtl,
                                                __nv_bfloat16* __restrict__ Oh,
                                                __nv_bfloat16* __restrict__ Ol) {
    extern __shared__ unsigned smw[];
    int qb = (int)gridDim.x - 1 - (int)blockIdx.x;   // heavy blocks first
    int h  = blockIdx.y;
    int hk = h / (NH / NKV);
    int tid  = threadIdx.x;
    int lane = tid & 31;
    int w    = tid >> 5;                // warp 0..7, owns rows w*16 + {gid, gid+8}
    int gid  = lane >> 2, tig = lane & 3;
    unsigned smb = sptr(smw);

    // Q tile: 128 x 128 hi/lo
#pragma unroll
    for (int j = 0; j < 8; j++) {
        int c = tid + 256 * j;
        int r = c >> 4, wo = c & 15;
        size_t g = (size_t)(qb * 128 + r) * DQ + h * HD + wo * 8;
        unsigned ds = (unsigned)(r * QSTR2 + wo * 4) * 4;
        CP_ASYNC16(smb + O2QH * 4 + ds, Qh + g);
        CP_ASYNC16(smb + O2QL * 4 + ds, Ql + g);
    }
#define ISSUE_KV2(kb_, st_) do {                                                  \
        for (int j = 0; j < 4; j++) {                                             \
            int c = tid + 256 * j;                                                \
            int r = c >> 4, wo = c & 15;                                          \
            size_t g = (size_t)((kb_) * 64 + r) * DKV + hk * HD + wo * 8;         \
            unsigned ds = (unsigned)((st_) * 64 * KSTR2 + r * KSTR2 + wo * 4) * 4;\
            CP_ASYNC16(smb + O2KH * 4 + ds, Kh + g);                              \
            CP_ASYNC16(smb + O2KL * 4 + ds, Kl + g);                              \
        }                                                                         \
        for (int j = 0; j < 4; j++) {                                             \
            int c = tid + 256 * j;                                                \
            int r = c >> 3, wo = c & 7;                                           \
            size_t g = (size_t)(hk * HD + r) * SEQ + (kb_) * 64 + wo * 8;         \
            unsigned ds = (unsigned)((st_) * 128 * VSTR2 + r * VSTR2 + wo * 4) * 4;\
            CP_ASYNC16(smb + O2VH * 4 + ds, Vth + g);                             \
            CP_ASYNC16(smb + O2VL * 4 + ds, Vtl + g);                             \
        }                                                                         \
    } while (0)

    ISSUE_KV2(0, 0);
    CP_COMMIT();

    float oacc[16][4];
#pragma unroll
    for (int nt = 0; nt < 16; nt++)
#pragma unroll
        for (int i = 0; i < 4; i++) oacc[nt][i] = 0.f;

    float m0 = -1e30f, m1 = -1e30f, l0 = 0.f, l1 = 0.f;
    const float scale = 0.08838834764831845f;
    const unsigned* QHs = smw + O2QH;
    const unsigned* QLs = smw + O2QL;

    const int NKB = 2 * qb + 2;
    const int rg0 = qb * 128 + w * 16 + gid;
    const int rg1 = rg0 + 8;

    for (int kb = 0; kb < NKB; kb++) {
        int st = kb & 1;
        asm volatile("cp.async.wait_group 0;\n");
        __syncthreads();
        if (kb + 1 < NKB) {
            ISSUE_KV2(kb + 1, 1 - st);
            CP_COMMIT();
        }

        const unsigned* KHs = smw + O2KH + st * 64 * KSTR2;
        const unsigned* KLs = smw + O2KL + st * 64 * KSTR2;
        const unsigned* VHs = smw + O2VH + st * 128 * VSTR2;
        const unsigned* VLs = smw + O2VL + st * 128 * VSTR2;

        // ---- S = Q @ K^T : warp tile 16 rows x 64 cols ----
        float sacc[8][4];
#pragma unroll
        for (int nt = 0; nt < 8; nt++)
#pragma unroll
            for (int i = 0; i < 4; i++) sacc[nt][i] = 0.f;

#pragma unroll
        for (int k16 = 0; k16 < 8; k16++) {
            int ab = (w * 16 + gid) * QSTR2 + 8 * k16 + tig;
            unsigned qa[4] = { QHs[ab], QHs[ab + 8 * QSTR2], QHs[ab + 4], QHs[ab + 8 * QSTR2 + 4] };
            unsigned ql[4] = { QLs[ab], QLs[ab + 8 * QSTR2], QLs[ab + 4], QLs[ab + 8 * QSTR2 + 4] };
#pragma unroll
            for (int nt = 0; nt < 8; nt++) {
                int nb2 = (nt * 8 + gid) * KSTR2 + 8 * k16 + tig;
                unsigned bh[2] = { KHs[nb2], KHs[nb2 + 4] };
                unsigned bl[2] = { KLs[nb2], KLs[nb2 + 4] };
                MMA_BF16(sacc[nt], qa, bh);
                MMA_BF16(sacc[nt], qa, bl);
                MMA_BF16(sacc[nt], ql, bh);
            }
        }

        // ---- warp-local online softmax ----
        bool diag = (kb >= 2 * qb);
        float mx0 = -1e30f, mx1 = -1e30f;
#pragma unroll
        for (int nt = 0; nt < 8; nt++) {
            float s0 = sacc[nt][0] * scale;
            float s1 = sacc[nt][1] * scale;
            float s2 = sacc[nt][2] * scale;
            float s3 = sacc[nt][3] * scale;
            if (diag) {
                int c0 = kb * 64 + nt * 8 + tig * 2;
                if (c0     > rg0) s0 = -1e30f;
                if (c0 + 1 > rg0) s1 = -1e30f;
                if (c0     > rg1) s2 = -1e30f;
                if (c0 + 1 > rg1) s3 = -1e30f;
            }
            sacc[nt][0] = s0; sacc[nt][1] = s1; sacc[nt][2] = s2; sacc[nt][3] = s3;
            mx0 = fmaxf(mx0, fmaxf(s0, s1));
            mx1 = fmaxf(mx1, fmaxf(s2, s3));
        }
        mx0 = fmaxf(mx0, __shfl_xor_sync(0xffffffffu, mx0, 1));
        mx0 = fmaxf(mx0, __shfl_xor_sync(0xffffffffu, mx0, 2));
        mx1 = fmaxf(mx1, __shfl_xor_sync(0xffffffffu, mx1, 1));
        mx1 = fmaxf(mx1, __shfl_xor_sync(0xffffffffu, mx1, 2));
        float mn0 = fmaxf(m0, mx0), mn1 = fmaxf(m1, mx1);
        float corr0 = __expf(m0 - mn0), corr1 = __expf(m1 - mn1);

        unsigned aPh[4][4], aPl[4][4];
        float la0 = 0.f, la1 = 0.f;
#pragma unroll
        for (int j = 0; j < 4; j++) {
#pragma unroll
            for (int half = 0; half < 2; half++) {
                int nt = 2 * j + half;
                float p0 = __expf(sacc[nt][0] - mn0);
                float p1 = __expf(sacc[nt][1] - mn0);
                float p2 = __expf(sacc[nt][2] - mn1);
                float p3 = __expf(sacc[nt][3] - mn1);
                la0 += p0 + p1;
                la1 += p2 + p3;
                packhl(p0, p1, aPh[j][2 * half],     aPl[j][2 * half]);
                packhl(p2, p3, aPh[j][2 * half + 1], aPl[j][2 * half + 1]);
            }
        }
        la0 += __shfl_xor_sync(0xffffffffu, la0, 1);
        la0 += __shfl_xor_sync(0xffffffffu, la0, 2);
        la1 += __shfl_xor_sync(0xffffffffu, la1, 1);
        la1 += __shfl_xor_sync(0xffffffffu, la1, 2);
        l0 = l0 * corr0 + la0;
        l1 = l1 * corr1 + la1;
        m0 = mn0; m1 = mn1;

#pragma unroll
        for (int nt = 0; nt < 16; nt++) {
            oacc[nt][0] *= corr0; oacc[nt][1] *= corr0;
            oacc[nt][2] *= corr1; oacc[nt][3] *= corr1;
        }

        // ---- O += P @ V (P in registers) ----
#pragma unroll
        for (int j = 0; j < 4; j++) {
#pragma unroll
            for (int nt = 0; nt < 16; nt++) {
                int vb = (nt * 8 + gid) * VSTR2 + 8 * j + tig;
                unsigned bh[2] = { VHs[vb], VHs[vb + 4] };
                unsigned bl[2] = { VLs[vb], VLs[vb + 4] };
                MMA_BF16(oacc[nt], aPh[j], bh);
                MMA_BF16(oacc[nt], aPh[j], bl);
                MMA_BF16(oacc[nt], aPl[j], bh);
            }
        }
    }
#undef ISSUE_KV2

    // ---- finalize ----
    float inv0 = 1.0f / l0;
    float inv1 = 1.0f / l1;
    int gr = qb * 128 + w * 16 + gid;
#pragma unroll
    for (int nt = 0; nt < 16; nt++) {
        int c = h * HD + nt * 8 + tig * 2;
        unsigned wh0, wl0, wh1, wl1;
        packhl(oacc[nt][0] * inv0, oacc[nt][1] * inv0, wh0, wl0);
        packhl(oacc[nt][2] * inv1, oacc[nt][3] * inv1, wh1, wl1);
        *reinterpret_cast<unsigned*>(&Oh[(size_t)gr * DQ + c])       = wh0;
        *reinterpret_cast<unsigned*>(&Oh[(size_t)(gr + 8) * DQ + c]) = wh1;
        *reinterpret_cast<unsigned*>(&Ol[(size_t)gr * DQ + c])       = wl0;
        *reinterpret_cast<unsigned*>(&Ol[(size_t)(gr + 8) * DQ + c]) = wl1;
    }
}

// ---------------- launch ----------------
extern "C" void kernel_launch(void* const* d_in, const int* in_sizes, int n_in,
                              void* d_out, int out_size) {
    const float* x    = (const float*)d_in[0];
    const int*   pos  = (const int*)d_in[1];
    const int*   qw_q = (const int*)d_in[2];
    const int*   qz_q = (const int*)d_in[3];
    const float* sc_q = (const float*)d_in[4];
    const float* b_q  = (const float*)d_in[5];
    const int*   qw_k = (const int*)d_in[6];
    const int*   qz_k = (const int*)d_in[7];
    const float* sc_k = (const float*)d_in[8];
    const float* b_k  = (const float*)d_in[9];
    const int*   qw_v = (const int*)d_in[10];
    const int*   qz_v = (const int*)d_in[11];
    const float* sc_v = (const float*)d_in[12];
    const float* b_v  = (const float*)d_in[13];
    const int*   qw_o = (const int*)d_in[14];
    const int*   qz_o = (const int*)d_in[15];
    const float* sc_o = (const float*)d_in[16];
    float* out = (float*)d_out;

    __nv_bfloat16 *WqT,*WkT,*WvT,*WoT,*Xh,*Xl,*Obh,*Obl;
    __nv_bfloat16 *Qbh,*Qbl,*Kbh,*Kbl,*Vth,*Vtl;
    float *Qb,*Kb,*Vb;
    cudaGetSymbolAddress((void**)&WqT, g_WqT);
    cudaGetSymbolAddress((void**)&WkT, g_WkT);
    cudaGetSymbolAddress((void**)&WvT, g_WvT);
    cudaGetSymbolAddress((void**)&WoT, g_WoT);
    cudaGetSymbolAddress((void**)&Xh, g_Xh);      cudaGetSymbolAddress((void**)&Xl, g_Xl);
    cudaGetSymbolAddress((void**)&Obh, g_Obh);    cudaGetSymbolAddress((void**)&Obl, g_Obl);
    cudaGetSymbolAddress((void**)&Qbh, g_Qbh);    cudaGetSymbolAddress((void**)&Qbl, g_Qbl);
    cudaGetSymbolAddress((void**)&Kbh, g_Kbh);    cudaGetSymbolAddress((void**)&Kbl, g_Kbl);
    cudaGetSymbolAddress((void**)&Vth, g_Vth);    cudaGetSymbolAddress((void**)&Vtl, g_Vtl);
    cudaGetSymbolAddress((void**)&Qb, g_Q);
    cudaGetSymbolAddress((void**)&Kb, g_K);
    cudaGetSymbolAddress((void**)&Vb, g_V);

    cudaFuncSetAttribute(gemmsQKV, cudaFuncAttributeMaxDynamicSharedMemorySize, SGEMM_SMEM);
    cudaFuncSetAttribute(gemmsO,   cudaFuncAttributeMaxDynamicSharedMemorySize, SGEMM_SMEM);
    cudaFuncSetAttribute(attn_bf2, cudaFuncAttributeMaxDynamicSharedMemorySize, ATTN2_SMEM);

    // dequant -> transposed INT bf16 weights (exact)
    {
        int t_q = DQ  * (HID / 8);
        int t_kv = DKV * (HID / 8);
        int t_o = HID * (DQ / 8);
        dequantTI_kernel<<<(t_q  + 255) / 256, 256>>>(qw_q, qz_q, WqT, HID, DQ);
        dequantTI_kernel<<<(t_kv + 255) / 256, 256>>>(qw_k, qz_k, WkT, HID, DKV);
        dequantTI_kernel<<<(t_kv + 255) / 256, 256>>>(qw_v, qz_v, WvT, HID, DKV);
        dequantTI_kernel<<<(t_o  + 255) / 256, 256>>>(qw_o, qz_o, WoT, DQ, HID);
    }

    // split activations
    {
        int n = SEQ * HID;
        splitb_kernel<<<(n + 255) / 256, 256>>>(x, Xh, Xl, n);
    }

    // fused Q/K/V projections (one launch, 576 CTAs)
    gemmsQKV<<<dim3(36, SEQ / 128), 256, SGEMM_SMEM>>>(
        Xh, Xl, WqT, WkT, WvT, sc_q, sc_k, sc_v, b_q, b_k, b_v, Qb, Kb, Vb);

    // RoPE + split
    {
        int total = SEQ * (NH + NKV) * (HD / 2);
        rope_split_kernel<<<(total + 255) / 256, 256>>>(Qb, Kb, pos, Qbh, Qbl, Kbh, Kbl);
    }
    vsplitT_kernel<<<dim3(DKV / 32, SEQ / 32), dim3(32, 8)>>>(Vb, Vth, Vtl);

    // attention (FA2 style, QB=128)
    attn_bf2<<<dim3(SEQ / 128, NH), 256, ATTN2_SMEM>>>(Qbh, Qbl, Kbh, Kbl, Vth, Vtl, Obh, Obl);

    // output projection
    gemmsO<<<dim3(HID / 128, SEQ / 128), 256, SGEMM_SMEM>>>(Obh, Obl, WoT, sc_o, nullptr, out);
}